// round 5
// baseline (speedup 1.0000x reference)
#include <cuda_runtime.h>

#define BB 16
#define CC 64
#define HH 64
#define WW 64
#define HW 4096

typedef unsigned long long ull;

__device__ float g_off[BB * 18 * HW];      // offsets from offset conv
__device__ float g_s[BB * CC * HW];        // branch-sum feature map
__device__ float g_w1t[576 * 64];          // w1 repacked: [k*64+c][o]

// ---- f32x2 packed helpers ------------------------------------------------
__device__ __forceinline__ void ffma2(ull& d, ull a, ull b) {
    asm("fma.rn.f32x2 %0, %1, %2, %0;" : "+l"(d) : "l"(a), "l"(b));
}
__device__ __forceinline__ ull pack2(float lo, float hi) {
    ull r;
    asm("mov.b64 %0, {%1, %2};" : "=l"(r) : "f"(lo), "f"(hi));
    return r;
}
__device__ __forceinline__ ull bcast2(float v) {
    ull r;
    asm("mov.b64 %0, {%1, %1};" : "=l"(r) : "f"(v));
    return r;
}
__device__ __forceinline__ float2 unpack2(ull v) {
    float2 r;
    asm("mov.b64 {%0, %1}, %2;" : "=f"(r.x), "=f"(r.y) : "l"(v));
    return r;
}

// ---------------------------------------------------------------------------
// Kernel 1: offset conv — 3x3, pad 1, Cin=64, Cout=18, plus bias
// ---------------------------------------------------------------------------
__global__ __launch_bounds__(256) void offset_conv_kernel(
    const float* __restrict__ x, const float* __restrict__ w_off,
    const float* __restrict__ b_off)
{
    __shared__ float ws[576 * 18];        // [tap][o]
    __shared__ float xs[4][18][19];

    int tid = threadIdx.x;
    int b   = blockIdx.y;
    int ty0 = (blockIdx.x >> 2) * 16;
    int tx0 = (blockIdx.x & 3) * 16;
    int ty  = tid >> 4, tx = tid & 15;

    for (int i = tid; i < 576 * 18; i += 256) {
        int tap = i / 18, o = i % 18;
        ws[i] = w_off[o * 576 + tap];
    }

    ull accp[9];
#pragma unroll
    for (int j = 0; j < 9; j++) accp[j] = 0ull;

    for (int cc0 = 0; cc0 < 64; cc0 += 4) {
        __syncthreads();
        for (int i = tid; i < 4 * 18 * 18; i += 256) {
            int c = i / 324, r = i % 324, yy = r / 18, xx = r % 18;
            int gy = ty0 - 1 + yy, gx = tx0 - 1 + xx;
            float v = 0.f;
            if (gy >= 0 && gy < 64 && gx >= 0 && gx < 64)
                v = x[((b * 64 + cc0 + c) * 64 + gy) * 64 + gx];
            xs[c][yy][xx] = v;
        }
        __syncthreads();
#pragma unroll
        for (int c = 0; c < 4; c++)
#pragma unroll
        for (int ky = 0; ky < 3; ky++)
#pragma unroll
        for (int kx = 0; kx < 3; kx++) {
            float xv = xs[c][ty + ky][tx + kx];
            ull xp = bcast2(xv);
            const ull* wp =
                (const ull*)&ws[(((cc0 + c) * 3 + ky) * 3 + kx) * 18];
#pragma unroll
            for (int j = 0; j < 9; j++)
                ffma2(accp[j], wp[j], xp);
        }
    }
    int ho = ty0 + ty, wo = tx0 + tx;
#pragma unroll
    for (int j = 0; j < 9; j++) {
        float2 a = unpack2(accp[j]);
        g_off[((b * 18 + 2 * j) * 64 + ho) * 64 + wo]     = a.x + b_off[2 * j];
        g_off[((b * 18 + 2 * j + 1) * 64 + ho) * 64 + wo] = a.y + b_off[2 * j + 1];
    }
}

// ---------------------------------------------------------------------------
// Kernel 2: repack w1 [o][c][3][3] -> g_w1t[(k*64+c)*64 + o]
// ---------------------------------------------------------------------------
__global__ void repack_w1_kernel(const float* __restrict__ w1)
{
    int i = blockIdx.x * 256 + threadIdx.x;
    if (i < 36864) {
        int o = i / 576, r = i % 576, c = r / 9, k = r % 9;
        g_w1t[(k * 64 + c) * 64 + o] = w1[i];
    }
}

// ---------------------------------------------------------------------------
// Kernel 3: fused deformable conv (3x3, pad 1) + BN1 + ReLU -> g_s
// v2: 32-pixel blocks; GEMM with warp-uniform oc-groups (8 oc per warp),
// 4 independent acc pairs per thread, broadcast weight LDS.128.
// ---------------------------------------------------------------------------
__global__ __launch_bounds__(256) void deform_kernel(
    const float* __restrict__ x,
    const float* __restrict__ g1, const float* __restrict__ b1,
    const float* __restrict__ m1, const float* __restrict__ v1)
{
    extern __shared__ float dsm[];
    float* val   = dsm;               // [576][32]
    float* wsh   = val + 576 * 32;    // [32][64]
    float* cw00  = wsh + 2048;        // [288]
    float* cw01  = cw00 + 288;
    float* cw10  = cw01 + 288;
    float* cw11  = cw10 + 288;
    float* scale = cw11 + 288;        // [64]
    float* bias  = scale + 64;        // [64]
    int*   cpos  = (int*)(bias + 64); // [288]

    int tid = threadIdx.x;
    int wo0 = blockIdx.x * 32;
    int ho  = blockIdx.y;
    int b   = blockIdx.z;

    if (tid < 64) {
        float sc   = g1[tid] * rsqrtf(v1[tid] + 1e-5f);
        scale[tid] = sc;
        bias[tid]  = b1[tid] - m1[tid] * sc;
    }
    for (int t = tid; t < 288; t += 256) {
        int k = t >> 5, px = t & 31;
        int ky = k / 3, kx = k % 3;
        int wo = wo0 + px;
        float dy = g_off[((b * 18 + 2 * k) * 64 + ho) * 64 + wo];
        float dx = g_off[((b * 18 + 2 * k + 1) * 64 + ho) * 64 + wo];
        float ys  = (float)(ho - 1 + ky) + dy;
        float xsm = (float)(wo - 1 + kx) + dx;
        float y0f = floorf(ys), x0f = floorf(xsm);
        float y1f = y0f + 1.f, x1f = x0f + 1.f;
        float wy1 = ys - y0f, wx1 = xsm - x0f;
        float wy0 = 1.f - wy1, wx0 = 1.f - wx1;
        bool vy0 = (y0f >= 0.f) && (y0f <= 63.f);
        bool vy1 = (y1f >= 0.f) && (y1f <= 63.f);
        bool vx0 = (x0f >= 0.f) && (x0f <= 63.f);
        bool vx1 = (x1f >= 0.f) && (x1f <= 63.f);
        cw00[t] = (vy0 && vx0) ? wy0 * wx0 : 0.f;
        cw01[t] = (vy0 && vx1) ? wy0 * wx1 : 0.f;
        cw10[t] = (vy1 && vx0) ? wy1 * wx0 : 0.f;
        cw11[t] = (vy1 && vx1) ? wy1 * wx1 : 0.f;
        int y0c = (int)fminf(fmaxf(y0f, 0.f), 63.f);
        int x0c = (int)fminf(fmaxf(x0f, 0.f), 63.f);
        int y1c = (int)fminf(fmaxf(y1f, 0.f), 63.f);
        int x1c = (int)fminf(fmaxf(x1f, 0.f), 63.f);
        cpos[t] = y0c | (x0c << 6) | (y1c << 12) | (x1c << 18);
    }
    __syncthreads();

    // bilinear gather: val[(k*64+c)*32 + px]
    for (int t = tid; t < 18432; t += 256) {
        int px = t & 31, c = (t >> 5) & 63, k = t >> 11;
        int pair = k * 32 + px;
        int p  = cpos[pair];
        int y0 = p & 63, x0 = (p >> 6) & 63;
        int y1 = (p >> 12) & 63, x1 = (p >> 18) & 63;
        const float* xb = x + (b * 64 + c) * HW;
        float v = cw00[pair] * xb[y0 * 64 + x0]
                + cw01[pair] * xb[y0 * 64 + x1]
                + cw10[pair] * xb[y1 * 64 + x0]
                + cw11[pair] * xb[y1 * 64 + x1];
        val[(k * 64 + c) * 32 + px] = v;
    }

    // GEMM: warp w -> ocs [8w, 8w+8); lane -> pixel
    int w8 = (tid >> 5) * 8;
    int px = tid & 31;
    ull acc[4];
#pragma unroll
    for (int i = 0; i < 4; i++) acc[i] = 0ull;

    for (int j = 0; j < 18; j++) {
        __syncthreads();
        for (int i = tid; i < 2048; i += 256)
            wsh[i] = g_w1t[j * 2048 + i];
        __syncthreads();
#pragma unroll 8
        for (int kcl = 0; kcl < 32; kcl++) {
            const ulonglong2* wp = (const ulonglong2*)&wsh[kcl * 64 + w8];
            ulonglong2 wA = wp[0], wB = wp[1];
            float xv = val[(j * 32 + kcl) * 32 + px];
            ull xp = bcast2(xv);
            ffma2(acc[0], wA.x, xp);
            ffma2(acc[1], wA.y, xp);
            ffma2(acc[2], wB.x, xp);
            ffma2(acc[3], wB.y, xp);
        }
    }
    int wo = wo0 + px;
#pragma unroll
    for (int i = 0; i < 4; i++) {
        float2 a = unpack2(acc[i]);
        int oc0 = w8 + 2 * i;
        float r0 = fmaxf(a.x * scale[oc0] + bias[oc0], 0.f);
        float r1 = fmaxf(a.y * scale[oc0 + 1] + bias[oc0 + 1], 0.f);
        g_s[((b * 64 + oc0) * 64 + ho) * 64 + wo]     = r0;
        g_s[((b * 64 + oc0 + 1) * 64 + ho) * 64 + wo] = r1;
    }
}

// ---------------------------------------------------------------------------
// Kernels 4/5: tiled conv, 16x8 pixel tiles, 4oc x 8px per thread.
// 3 CTAs/SM (24 warps) for latency hiding. No in-loop x packing; weight
// broadcast pairs via 4 cheap movs per kx.
// MODE 0: g_s += relu(bn(conv_KSZ(x)));  MODE 1: dst = relu(bn(conv(g_s))+resid)
// ---------------------------------------------------------------------------
template <int KSZ, int MODE>
__global__ __launch_bounds__(256, 3) void conv_tiled_kernel(
    const float* __restrict__ src, const float* __restrict__ w,
    const float* __restrict__ gg, const float* __restrict__ bbn,
    const float* __restrict__ mmn, const float* __restrict__ vvn,
    const float* __restrict__ resid, float* __restrict__ dst)
{
    constexpr int PAD = KSZ / 2;
    constexpr int TH  = 16, TW = 8;
    constexpr int XH  = TH + KSZ - 1;
    constexpr int XW  = TW + KSZ - 1;
    constexpr int XWP = (XW % 4 == 0) ? XW + 2 : XW;  // conflict-free stride
    constexpr int KK  = KSZ * KSZ;
    constexpr int NP  = XW / 2;             // even pairs
    constexpr int NOP = TW / 2 + KSZ / 2 - 1;  // odd pairs needed
    constexpr int NJ  = TW / 2;             // output pairs per thread

    extern __shared__ float sm[];
    float* xsA   = sm;                         // [4][XH][XWP]
    float* xsB   = xsA + 4 * XH * XWP;         // shifted +1
    float* wsm   = xsB + 4 * XH * XWP;         // [4*KK][64]
    float* scale = wsm + 4 * KK * 64;
    float* bias  = scale + 64;

    int tid = threadIdx.x;
    int b   = blockIdx.y;
    int ty0 = (blockIdx.x >> 3) * TH;          // 4 row tiles
    int tx0 = (blockIdx.x & 7) * TW;           // 8 col strips
    int ty  = tid >> 4, tx = tid & 15;

    if (tid < 64) {
        float sc   = gg[tid] * rsqrtf(vvn[tid] + 1e-5f);
        scale[tid] = sc;
        bias[tid]  = bbn[tid] - mmn[tid] * sc;
    }

    const float* in = (MODE == 0) ? src : (const float*)g_s;

    ull accp[4][NJ];
#pragma unroll
    for (int m = 0; m < 4; m++)
#pragma unroll
        for (int j = 0; j < NJ; j++) accp[m][j] = 0ull;

    for (int cc0 = 0; cc0 < 64; cc0 += 4) {
        __syncthreads();
        for (int i = tid; i < 4 * XH * XW; i += 256) {
            int c = i / (XH * XW), r = i % (XH * XW), yy = r / XW, xx = r % XW;
            int gy = ty0 - PAD + yy, gx = tx0 - PAD + xx;
            const float* inb = in + ((b * 64 + cc0 + c) * 64) * 64;
            float vA = 0.f, vB = 0.f;
            if (gy >= 0 && gy < 64) {
                if (gx >= 0 && gx < 64)         vA = inb[gy * 64 + gx];
                if (gx + 1 >= 0 && gx + 1 < 64) vB = inb[gy * 64 + gx + 1];
            }
            xsA[(c * XH + yy) * XWP + xx] = vA;
            xsB[(c * XH + yy) * XWP + xx] = vB;
        }
        for (int i = tid; i < 64 * 4 * KK; i += 256) {
            int o = i / (4 * KK), r = i % (4 * KK), c = r / KK, kk = r % KK;
            wsm[(c * KK + kk) * 64 + o] = w[(o * 64 + cc0 + c) * KK + kk];
        }
        __syncthreads();
#pragma unroll
        for (int c = 0; c < 4; c++)
#pragma unroll
        for (int ky = 0; ky < KSZ; ky++) {
            const float* rowA = xsA + (c * XH + tx + ky) * XWP;
            const float* rowB = xsB + (c * XH + tx + ky) * XWP;
            ull ep[NP], op[NOP];
#pragma unroll
            for (int i2 = 0; i2 < NP; i2++)
                ep[i2] = *(const ull*)(rowA + 2 * i2);
#pragma unroll
            for (int i2 = 0; i2 < NOP; i2++)
                op[i2] = *(const ull*)(rowB + 2 * i2);
#pragma unroll
            for (int kx = 0; kx < KSZ; kx++) {
                float4 wv = *(const float4*)&wsm[(c * KK + ky * KSZ + kx) * 64 + ty * 4];
                ull w0 = bcast2(wv.x), w1 = bcast2(wv.y);
                ull w2 = bcast2(wv.z), w3 = bcast2(wv.w);
                int t = kx >> 1;
                const ull* xp = (kx & 1) ? &op[t] : &ep[t];
#pragma unroll
                for (int j = 0; j < NJ; j++) {
                    ull xv = xp[j];
                    ffma2(accp[0][j], w0, xv);
                    ffma2(accp[1][j], w1, xv);
                    ffma2(accp[2][j], w2, xv);
                    ffma2(accp[3][j], w3, xv);
                }
            }
        }
    }

    int row = ty0 + tx;
#pragma unroll
    for (int m = 0; m < 4; m++) {
        int oc   = ty * 4 + m;
        int base = ((b * 64 + oc) * 64 + row) * 64 + tx0;
        float sc = scale[oc], bi = bias[oc];
#pragma unroll
        for (int j = 0; j < NJ; j++) {
            float2 a = unpack2(accp[m][j]);
            float r0 = a.x * sc + bi;
            float r1 = a.y * sc + bi;
            if (MODE == 0) {
                float2 old = *(float2*)&g_s[base + 2 * j];
                float2 nv  = make_float2(fmaxf(r0, 0.f) + old.x,
                                         fmaxf(r1, 0.f) + old.y);
                *(float2*)&g_s[base + 2 * j] = nv;
            } else {
                float2 rs = *(const float2*)&resid[base + 2 * j];
                float2 nv = make_float2(fmaxf(r0 + rs.x, 0.f),
                                        fmaxf(r1 + rs.y, 0.f));
                *(float2*)&dst[base + 2 * j] = nv;
            }
        }
    }
}

// ---------------------------------------------------------------------------
extern "C" void kernel_launch(void* const* d_in, const int* in_sizes, int n_in,
                              void* d_out, int out_size)
{
    const float* x     = (const float*)d_in[0];
    const float* w_off = (const float*)d_in[1];
    const float* b_off = (const float*)d_in[2];
    const float* w1    = (const float*)d_in[3];
    const float* g1    = (const float*)d_in[4];
    const float* b1    = (const float*)d_in[5];
    const float* m1    = (const float*)d_in[6];
    const float* v1    = (const float*)d_in[7];
    const float* w3    = (const float*)d_in[8];
    const float* g3    = (const float*)d_in[9];
    const float* b3    = (const float*)d_in[10];
    const float* m3    = (const float*)d_in[11];
    const float* v3    = (const float*)d_in[12];
    const float* w2    = (const float*)d_in[13];
    const float* g2    = (const float*)d_in[14];
    const float* b2    = (const float*)d_in[15];
    const float* m2    = (const float*)d_in[16];
    const float* v2    = (const float*)d_in[17];
    float* out = (float*)d_out;

    // dynamic smem sizes
    const int smem5 = (2 * 4 * 20 * 14 + 4 * 25 * 64 + 128) * 4;  // 35,072
    const int smem3 = (2 * 4 * 18 * 10 + 4 * 9 * 64 + 128) * 4;   // 15,488
    const int smemD = (576 * 32 + 2048 + 4 * 288 + 128 + 288) * 4; // 88,192
    static bool attr_set = false;
    if (!attr_set) {
        cudaFuncSetAttribute(conv_tiled_kernel<5, 0>,
                             cudaFuncAttributeMaxDynamicSharedMemorySize, smem5);
        cudaFuncSetAttribute(conv_tiled_kernel<3, 1>,
                             cudaFuncAttributeMaxDynamicSharedMemorySize, smem3);
        cudaFuncSetAttribute(deform_kernel,
                             cudaFuncAttributeMaxDynamicSharedMemorySize, smemD);
        attr_set = true;
    }

    offset_conv_kernel<<<dim3(16, 16), 256>>>(x, w_off, b_off);
    repack_w1_kernel<<<144, 256>>>(w1);
    deform_kernel<<<dim3(2, 64, 16), 256, smemD>>>(x, g1, b1, m1, v1);
    conv_tiled_kernel<5, 0><<<dim3(32, 16), 256, smem5>>>(x, w3, g3, b3, m3, v3,
                                                          nullptr, nullptr);
    conv_tiled_kernel<3, 1><<<dim3(32, 16), 256, smem3>>>(nullptr, w2, g2, b2,
                                                          m2, v2, x, out);
}

// round 6
// speedup vs baseline: 1.8405x; 1.8405x over previous
#include <cuda_runtime.h>

#define HW 4096
typedef unsigned long long ull;

__device__ float g_off[16 * 18 * HW];      // offsets from offset conv
__device__ float g_s[16 * 64 * HW];        // branch-sum feature map
__device__ float g_xt[16 * 64 * HW];       // x transposed to NHWC [b][y][x][c]
__device__ unsigned g_wpk5[102400];        // w3 fragment-packed (tf32 bits)
__device__ unsigned g_wpk1[36864];         // w1 fragment-packed (tf32 bits)

// ---- scalar packed fp32 helpers (offset conv + final conv) ---------------
__device__ __forceinline__ void ffma2(ull& d, ull a, ull b) {
    asm("fma.rn.f32x2 %0, %1, %2, %0;" : "+l"(d) : "l"(a), "l"(b));
}
__device__ __forceinline__ ull bcast2(float v) {
    ull r;
    asm("mov.b64 %0, {%1, %1};" : "=l"(r) : "f"(v));
    return r;
}
__device__ __forceinline__ float2 unpack2(ull v) {
    float2 r;
    asm("mov.b64 {%0, %1}, %2;" : "=f"(r.x), "=f"(r.y) : "l"(v));
    return r;
}

// ---- tf32 mma helpers ------------------------------------------------------
__device__ __forceinline__ unsigned f2tf(float f) {
    unsigned u;
    asm("cvt.rna.tf32.f32 %0, %1;" : "=r"(u) : "f"(f));
    return u;
}
__device__ __forceinline__ void mma8(float* d, const unsigned* a, const unsigned* b) {
    asm("mma.sync.aligned.m16n8k8.row.col.f32.tf32.tf32.f32 "
        "{%0,%1,%2,%3},{%4,%5,%6,%7},{%8,%9},{%0,%1,%2,%3};"
        : "+f"(d[0]), "+f"(d[1]), "+f"(d[2]), "+f"(d[3])
        : "r"(a[0]), "r"(a[1]), "r"(a[2]), "r"(a[3]), "r"(b[0]), "r"(b[1]));
}

// ---------------------------------------------------------------------------
// Transpose x NCHW -> NHWC (g_xt), one (b, y) row per block
// ---------------------------------------------------------------------------
__global__ __launch_bounds__(256) void transpose_kernel(const float* __restrict__ x)
{
    __shared__ float t[64][65];
    int tid = threadIdx.x;
    int y = blockIdx.x, b = blockIdx.y;
    const float* xb = x + (b * 64) * HW + y * 64;
#pragma unroll
    for (int i = 0; i < 16; i++) {
        int c = i * 4 + (tid >> 6), xc = tid & 63;
        t[xc][c] = xb[c * HW + xc];
    }
    __syncthreads();
    float* ob = g_xt + ((b * 64 + y) * 64) * 64;
#pragma unroll
    for (int i = 0; i < 16; i++) {
        int xc = i * 4 + (tid >> 6), c = tid & 63;
        ob[xc * 64 + c] = t[xc][c];
    }
}

// ---------------------------------------------------------------------------
// Weight repacks into mma A-fragment order (tf32-rounded)
// frag reg r, lane l: oc = strip*16 + l/4 + (r&1)*8 ; k += (r>>1)*4 + l%4
// ---------------------------------------------------------------------------
__global__ void repack_wpk5_kernel(const float* __restrict__ w3)
{
    int i = blockIdx.x * 256 + threadIdx.x;
    if (i < 102400) {
        int r = i & 3, lane = (i >> 2) & 31, strip = (i >> 7) & 3;
        int c8 = (i >> 9) & 1, cblk = (i >> 10) & 3, tap = i >> 12;
        int oc = strip * 16 + (lane >> 2) + (r & 1) * 8;
        int c  = cblk * 16 + c8 * 8 + (lane & 3) + (r >> 1) * 4;
        g_wpk5[i] = f2tf(w3[(oc * 64 + c) * 25 + tap]);
    }
}
__global__ void repack_wpk1_kernel(const float* __restrict__ w1)
{
    int i = blockIdx.x * 256 + threadIdx.x;
    if (i < 36864) {
        int r = i & 3, lane = (i >> 2) & 31, strip = (i >> 7) & 3, kstep = i >> 9;
        int oc = strip * 16 + (lane >> 2) + (r & 1) * 8;
        int K  = kstep * 8 + (lane & 3) + (r >> 1) * 4;
        int tap = K >> 6, c = K & 63;
        g_wpk1[i] = f2tf(w1[(oc * 64 + c) * 9 + tap]);
    }
}

// ---------------------------------------------------------------------------
// Kernel: offset conv — 3x3, pad 1, Cin=64, Cout=18, plus bias (fp32 FFMA2)
// ---------------------------------------------------------------------------
__global__ __launch_bounds__(256) void offset_conv_kernel(
    const float* __restrict__ x, const float* __restrict__ w_off,
    const float* __restrict__ b_off)
{
    __shared__ float ws[576 * 18];
    __shared__ float xs[4][18][19];

    int tid = threadIdx.x;
    int b   = blockIdx.y;
    int ty0 = (blockIdx.x >> 2) * 16;
    int tx0 = (blockIdx.x & 3) * 16;
    int ty  = tid >> 4, tx = tid & 15;

    for (int i = tid; i < 576 * 18; i += 256) {
        int tap = i / 18, o = i % 18;
        ws[i] = w_off[o * 576 + tap];
    }

    ull accp[9];
#pragma unroll
    for (int j = 0; j < 9; j++) accp[j] = 0ull;

    for (int cc0 = 0; cc0 < 64; cc0 += 4) {
        __syncthreads();
        for (int i = tid; i < 4 * 18 * 18; i += 256) {
            int c = i / 324, r = i % 324, yy = r / 18, xx = r % 18;
            int gy = ty0 - 1 + yy, gx = tx0 - 1 + xx;
            float v = 0.f;
            if (gy >= 0 && gy < 64 && gx >= 0 && gx < 64)
                v = x[((b * 64 + cc0 + c) * 64 + gy) * 64 + gx];
            xs[c][yy][xx] = v;
        }
        __syncthreads();
#pragma unroll
        for (int c = 0; c < 4; c++)
#pragma unroll
        for (int ky = 0; ky < 3; ky++)
#pragma unroll
        for (int kx = 0; kx < 3; kx++) {
            float xv = xs[c][ty + ky][tx + kx];
            ull xp = bcast2(xv);
            const ull* wp = (const ull*)&ws[(((cc0 + c) * 3 + ky) * 3 + kx) * 18];
#pragma unroll
            for (int j = 0; j < 9; j++)
                ffma2(accp[j], wp[j], xp);
        }
    }
    int ho = ty0 + ty, wo = tx0 + tx;
#pragma unroll
    for (int j = 0; j < 9; j++) {
        float2 a = unpack2(accp[j]);
        g_off[((b * 18 + 2 * j) * 64 + ho) * 64 + wo]     = a.x + b_off[2 * j];
        g_off[((b * 18 + 2 * j + 1) * 64 + ho) * 64 + wo] = a.y + b_off[2 * j + 1];
    }
}

// ---------------------------------------------------------------------------
// Deformable conv (3x3, pad 1) + BN1 + ReLU -> g_s, tf32 mma GEMM
// One block per (ho, b): 64 output pixels, 64 ocs. K = 576 (tap*64+c).
// Gather reads NHWC g_xt with float4 over channels.
// ---------------------------------------------------------------------------
__global__ __launch_bounds__(256) void deform_mma_kernel(
    const float* __restrict__ g1, const float* __restrict__ b1,
    const float* __restrict__ m1, const float* __restrict__ v1)
{
    extern __shared__ unsigned dm[];
    unsigned* val = dm;                          // [576][72]
    float* cw00   = (float*)(dm + 41472);        // [576]
    float* cw01   = cw00 + 576;
    float* cw10   = cw01 + 576;
    float* cw11   = cw10 + 576;
    int*   cpos   = (int*)(cw11 + 576);          // [576]
    float* scale  = (float*)(cpos + 576);        // [64]
    float* bias   = scale + 64;                  // [64]
    unsigned* wsm = (unsigned*)(bias + 64);      // [4096] (8 ksteps of frags)

    int tid = threadIdx.x;
    int l   = tid & 31, wp = tid >> 5;
    int ho  = blockIdx.x, b = blockIdx.y;

    if (tid < 64) {
        float sc   = g1[tid] * rsqrtf(v1[tid] + 1e-5f);
        scale[tid] = sc;
        bias[tid]  = b1[tid] - m1[tid] * sc;
    }
    for (int t = tid; t < 576; t += 256) {
        int k = t >> 6, px = t & 63;
        int ky = k / 3, kx = k % 3;
        int wo = px;
        float dy = g_off[((b * 18 + 2 * k) * 64 + ho) * 64 + wo];
        float dx = g_off[((b * 18 + 2 * k + 1) * 64 + ho) * 64 + wo];
        float ys  = (float)(ho - 1 + ky) + dy;
        float xsm = (float)(wo - 1 + kx) + dx;
        float y0f = floorf(ys), x0f = floorf(xsm);
        float y1f = y0f + 1.f, x1f = x0f + 1.f;
        float wy1 = ys - y0f, wx1 = xsm - x0f;
        float wy0 = 1.f - wy1, wx0 = 1.f - wx1;
        bool vy0 = (y0f >= 0.f) && (y0f <= 63.f);
        bool vy1 = (y1f >= 0.f) && (y1f <= 63.f);
        bool vx0 = (x0f >= 0.f) && (x0f <= 63.f);
        bool vx1 = (x1f >= 0.f) && (x1f <= 63.f);
        cw00[t] = (vy0 && vx0) ? wy0 * wx0 : 0.f;
        cw01[t] = (vy0 && vx1) ? wy0 * wx1 : 0.f;
        cw10[t] = (vy1 && vx0) ? wy1 * wx0 : 0.f;
        cw11[t] = (vy1 && vx1) ? wy1 * wx1 : 0.f;
        int y0c = (int)fminf(fmaxf(y0f, 0.f), 63.f);
        int x0c = (int)fminf(fmaxf(x0f, 0.f), 63.f);
        int y1c = (int)fminf(fmaxf(y1f, 0.f), 63.f);
        int x1c = (int)fminf(fmaxf(x1f, 0.f), 63.f);
        cpos[t] = y0c | (x0c << 6) | (y1c << 12) | (x1c << 18);
    }
    __syncthreads();

    // gather: task = (k, px, cgroup of 16 channels), NHWC float4 loads
    for (int it = 0; it < 9; it++) {
        int t  = tid + it * 256;
        int cg = t & 3, px = (t >> 2) & 63, k = t >> 8;
        int pair = k * 64 + px;
        int p  = cpos[pair];
        float w00 = cw00[pair], w01 = cw01[pair];
        float w10 = cw10[pair], w11 = cw11[pair];
        int y0 = p & 63, x0 = (p >> 6) & 63;
        int y1 = (p >> 12) & 63, x1 = (p >> 18) & 63;
        const float4* p00 = (const float4*)(g_xt + (((b * 64 + y0) * 64 + x0) * 64) + cg * 16);
        const float4* p01 = (const float4*)(g_xt + (((b * 64 + y0) * 64 + x1) * 64) + cg * 16);
        const float4* p10 = (const float4*)(g_xt + (((b * 64 + y1) * 64 + x0) * 64) + cg * 16);
        const float4* p11 = (const float4*)(g_xt + (((b * 64 + y1) * 64 + x1) * 64) + cg * 16);
        unsigned* vout = val + (k * 64 + cg * 16) * 72 + px;
#pragma unroll
        for (int i = 0; i < 4; i++) {
            float4 a = p00[i], bq = p01[i], cq = p10[i], dq = p11[i];
            float r0 = w00 * a.x + w01 * bq.x + w10 * cq.x + w11 * dq.x;
            float r1 = w00 * a.y + w01 * bq.y + w10 * cq.y + w11 * dq.y;
            float r2 = w00 * a.z + w01 * bq.z + w10 * cq.z + w11 * dq.z;
            float r3 = w00 * a.w + w01 * bq.w + w10 * cq.w + w11 * dq.w;
            vout[(i * 4 + 0) * 72] = f2tf(r0);
            vout[(i * 4 + 1) * 72] = f2tf(r1);
            vout[(i * 4 + 2) * 72] = f2tf(r2);
            vout[(i * 4 + 3) * 72] = f2tf(r3);
        }
    }
    __syncthreads();

    // GEMM: out[64oc][64px] = W1[64][576] * val[576][64]; warp wp -> px group
    float acc[4][4];
#pragma unroll
    for (int s = 0; s < 4; s++)
#pragma unroll
        for (int r = 0; r < 4; r++) acc[s][r] = 0.f;

    const unsigned* vb = val + (l & 3) * 72 + wp * 8 + (l >> 2);

    for (int kc = 0; kc < 9; kc++) {
        __syncthreads();
        for (int i4 = tid; i4 < 1024; i4 += 256)
            ((uint4*)wsm)[i4] = ((const uint4*)(g_wpk1 + kc * 4096))[i4];
        __syncthreads();
#pragma unroll
        for (int ks = 0; ks < 8; ks++) {
            int kstep = kc * 8 + ks;
            unsigned A[4][4];
#pragma unroll
            for (int s = 0; s < 4; s++)
                *(uint4*)A[s] = *(const uint4*)(wsm + (ks * 4 + s) * 128 + l * 4);
            unsigned bf[2];
            bf[0] = vb[kstep * 576];
            bf[1] = vb[kstep * 576 + 288];
#pragma unroll
            for (int s = 0; s < 4; s++) mma8(acc[s], A[s], bf);
        }
    }

    int col = wp * 8 + (l & 3) * 2;
#pragma unroll
    for (int s = 0; s < 4; s++) {
        int oc0 = s * 16 + (l >> 2);
        int oc1 = oc0 + 8;
        float sc0 = scale[oc0], bi0 = bias[oc0];
        float sc1 = scale[oc1], bi1 = bias[oc1];
        float2 v0 = make_float2(fmaxf(acc[s][0] * sc0 + bi0, 0.f),
                                fmaxf(acc[s][1] * sc0 + bi0, 0.f));
        float2 v1 = make_float2(fmaxf(acc[s][2] * sc1 + bi1, 0.f),
                                fmaxf(acc[s][3] * sc1 + bi1, 0.f));
        *(float2*)&g_s[((b * 64 + oc0) * 64 + ho) * 64 + col] = v0;
        *(float2*)&g_s[((b * 64 + oc1) * 64 + ho) * 64 + col] = v1;
    }
}

// ---------------------------------------------------------------------------
// conv5 (5x5, pad 2) + BN3 + ReLU, accumulated into g_s — tf32 mma implicit GEMM
// Block: 8 rows x 16 cols, 64 ocs. Warp -> 1 output row (2 px groups).
// ---------------------------------------------------------------------------
__global__ __launch_bounds__(256) void conv5_mma_kernel(
    const float* __restrict__ x,
    const float* __restrict__ gg, const float* __restrict__ bbn,
    const float* __restrict__ mmn, const float* __restrict__ vvn)
{
    extern __shared__ unsigned cm[];
    unsigned* xs  = cm;                      // [16][12][22]
    unsigned* wfr = cm + 4224;               // [5 kx][2 c8][4 strip][128]
    float* scale  = (float*)(cm + 4224 + 5120);
    float* bias   = scale + 64;

    int tid = threadIdx.x;
    int l   = tid & 31, wp = tid >> 5;
    int b   = blockIdx.y;
    int by0 = (blockIdx.x >> 2) * 8;
    int bx0 = (blockIdx.x & 3) * 16;

    if (tid < 64) {
        float sc   = gg[tid] * rsqrtf(vvn[tid] + 1e-5f);
        scale[tid] = sc;
        bias[tid]  = bbn[tid] - mmn[tid] * sc;
    }

    float acc[4][2][4];
#pragma unroll
    for (int s = 0; s < 4; s++)
#pragma unroll
        for (int g = 0; g < 2; g++)
#pragma unroll
            for (int r = 0; r < 4; r++) acc[s][g][r] = 0.f;

    const unsigned* bbase = xs + (l & 3) * 264 + wp * 22 + (l >> 2);

    for (int cblk = 0; cblk < 4; cblk++) {
        __syncthreads();
        for (int i = tid; i < 3840; i += 256) {
            int c = i / 240, rr = i % 240, yy = rr / 20, xx = rr % 20;
            int gy = by0 - 2 + yy, gx = bx0 - 2 + xx;
            float v = 0.f;
            if (gy >= 0 && gy < 64 && gx >= 0 && gx < 64)
                v = x[((b * 64 + cblk * 16 + c) * 64 + gy) * 64 + gx];
            xs[(c * 12 + yy) * 22 + xx] = f2tf(v);
        }
        for (int ky = 0; ky < 5; ky++) {
            __syncthreads();
            for (int i4 = tid; i4 < 1280; i4 += 256) {
                int tl = i4 >> 8, rest = i4 & 255;
                ((uint4*)wfr)[i4] =
                    ((const uint4*)(g_wpk5 + (ky * 5 + tl) * 4096 + cblk * 1024))[rest];
            }
            __syncthreads();
#pragma unroll
            for (int kx = 0; kx < 5; kx++) {
#pragma unroll
                for (int c8 = 0; c8 < 2; c8++) {
                    unsigned A[4][4];
#pragma unroll
                    for (int s = 0; s < 4; s++)
                        *(uint4*)A[s] = *(const uint4*)(wfr + (kx * 2 + c8) * 512 + s * 128 + l * 4);
#pragma unroll
                    for (int g = 0; g < 2; g++) {
                        unsigned bf[2];
                        bf[0] = bbase[c8 * 2112 + ky * 22 + g * 8 + kx];
                        bf[1] = bbase[c8 * 2112 + 1056 + ky * 22 + g * 8 + kx];
#pragma unroll
                        for (int s = 0; s < 4; s++) mma8(acc[s][g], A[s], bf);
                    }
                }
            }
        }
    }

    // epilogue: g_s += relu(bn(acc))
    int row_g = by0 + wp;
#pragma unroll
    for (int s = 0; s < 4; s++) {
#pragma unroll
        for (int g = 0; g < 2; g++) {
            int oc0 = s * 16 + (l >> 2);
            int oc1 = oc0 + 8;
            int col = bx0 + g * 8 + (l & 3) * 2;
            float sc0 = scale[oc0], bi0 = bias[oc0];
            float sc1 = scale[oc1], bi1 = bias[oc1];
            float* a0 = &g_s[((b * 64 + oc0) * 64 + row_g) * 64 + col];
            float* a1 = &g_s[((b * 64 + oc1) * 64 + row_g) * 64 + col];
            float2 o0 = *(float2*)a0;
            float2 o1 = *(float2*)a1;
            o0.x += fmaxf(acc[s][g][0] * sc0 + bi0, 0.f);
            o0.y += fmaxf(acc[s][g][1] * sc0 + bi0, 0.f);
            o1.x += fmaxf(acc[s][g][2] * sc1 + bi1, 0.f);
            o1.y += fmaxf(acc[s][g][3] * sc1 + bi1, 0.f);
            *(float2*)a0 = o0;
            *(float2*)a1 = o1;
        }
    }
}

// ---------------------------------------------------------------------------
// Final conv: 3x3, pad 1, on g_s, + BN2 + identity residual + ReLU (fp32 FFMA2)
// ---------------------------------------------------------------------------
__global__ __launch_bounds__(256, 3) void conv3_final_kernel(
    const float* __restrict__ w,
    const float* __restrict__ gg, const float* __restrict__ bbn,
    const float* __restrict__ mmn, const float* __restrict__ vvn,
    const float* __restrict__ resid, float* __restrict__ dst)
{
    constexpr int KSZ = 3, PAD = 1;
    constexpr int TH = 16, TW = 8;
    constexpr int XH = TH + KSZ - 1;     // 18
    constexpr int XW = TW + KSZ - 1;     // 10
    constexpr int XWP = XW;              // 10, gcd(10,32)=2
    constexpr int KK = KSZ * KSZ;
    constexpr int NP = XW / 2;           // 5
    constexpr int NOP = TW / 2 + KSZ / 2 - 1;  // 4
    constexpr int NJ = TW / 2;           // 4

    extern __shared__ float sm[];
    float* xsA   = sm;
    float* xsB   = xsA + 4 * XH * XWP;
    float* wsm   = xsB + 4 * XH * XWP;
    float* scale = wsm + 4 * KK * 64;
    float* bias  = scale + 64;

    int tid = threadIdx.x;
    int b   = blockIdx.y;
    int ty0 = (blockIdx.x >> 3) * TH;
    int tx0 = (blockIdx.x & 7) * TW;
    int ty  = tid >> 4, tx = tid & 15;

    if (tid < 64) {
        float sc   = gg[tid] * rsqrtf(vvn[tid] + 1e-5f);
        scale[tid] = sc;
        bias[tid]  = bbn[tid] - mmn[tid] * sc;
    }

    ull accp[4][NJ];
#pragma unroll
    for (int m = 0; m < 4; m++)
#pragma unroll
        for (int j = 0; j < NJ; j++) accp[m][j] = 0ull;

    for (int cc0 = 0; cc0 < 64; cc0 += 4) {
        __syncthreads();
        for (int i = tid; i < 4 * XH * XW; i += 256) {
            int c = i / (XH * XW), r = i % (XH * XW), yy = r / XW, xx = r % XW;
            int gy = ty0 - PAD + yy, gx = tx0 - PAD + xx;
            const float* inb = g_s + ((b * 64 + cc0 + c) * 64) * 64;
            float vA = 0.f, vB = 0.f;
            if (gy >= 0 && gy < 64) {
                if (gx >= 0 && gx < 64)         vA = inb[gy * 64 + gx];
                if (gx + 1 >= 0 && gx + 1 < 64) vB = inb[gy * 64 + gx + 1];
            }
            xsA[(c * XH + yy) * XWP + xx] = vA;
            xsB[(c * XH + yy) * XWP + xx] = vB;
        }
        for (int i = tid; i < 64 * 4 * KK; i += 256) {
            int o = i / (4 * KK), r = i % (4 * KK), c = r / KK, kk = r % KK;
            wsm[(c * KK + kk) * 64 + o] = w[(o * 64 + cc0 + c) * KK + kk];
        }
        __syncthreads();
#pragma unroll
        for (int c = 0; c < 4; c++)
#pragma unroll
        for (int ky = 0; ky < KSZ; ky++) {
            const float* rowA = xsA + (c * XH + tx + ky) * XWP;
            const float* rowB = xsB + (c * XH + tx + ky) * XWP;
            ull ep[NP], op[NOP];
#pragma unroll
            for (int i2 = 0; i2 < NP; i2++)
                ep[i2] = *(const ull*)(rowA + 2 * i2);
#pragma unroll
            for (int i2 = 0; i2 < NOP; i2++)
                op[i2] = *(const ull*)(rowB + 2 * i2);
#pragma unroll
            for (int kx = 0; kx < KSZ; kx++) {
                float4 wv = *(const float4*)&wsm[(c * KK + ky * KSZ + kx) * 64 + ty * 4];
                ull w0 = bcast2(wv.x), w1 = bcast2(wv.y);
                ull w2 = bcast2(wv.z), w3 = bcast2(wv.w);
                int t = kx >> 1;
                const ull* xp = (kx & 1) ? &op[t] : &ep[t];
#pragma unroll
                for (int j = 0; j < NJ; j++) {
                    ull xv = xp[j];
                    ffma2(accp[0][j], w0, xv);
                    ffma2(accp[1][j], w1, xv);
                    ffma2(accp[2][j], w2, xv);
                    ffma2(accp[3][j], w3, xv);
                }
            }
        }
    }

    int row = ty0 + tx;
#pragma unroll
    for (int m = 0; m < 4; m++) {
        int oc   = ty * 4 + m;
        int base = ((b * 64 + oc) * 64 + row) * 64 + tx0;
        float sc = scale[oc], bi = bias[oc];
#pragma unroll
        for (int j = 0; j < NJ; j++) {
            float2 a = unpack2(accp[m][j]);
            float2 rs = *(const float2*)&resid[base + 2 * j];
            float2 nv = make_float2(fmaxf(a.x * sc + bi + rs.x, 0.f),
                                    fmaxf(a.y * sc + bi + rs.y, 0.f));
            *(float2*)&dst[base + 2 * j] = nv;
        }
    }
}

// ---------------------------------------------------------------------------
extern "C" void kernel_launch(void* const* d_in, const int* in_sizes, int n_in,
                              void* d_out, int out_size)
{
    const float* x     = (const float*)d_in[0];
    const float* w_off = (const float*)d_in[1];
    const float* b_off = (const float*)d_in[2];
    const float* w1    = (const float*)d_in[3];
    const float* g1    = (const float*)d_in[4];
    const float* b1    = (const float*)d_in[5];
    const float* m1    = (const float*)d_in[6];
    const float* v1    = (const float*)d_in[7];
    const float* w3    = (const float*)d_in[8];
    const float* g3    = (const float*)d_in[9];
    const float* b3    = (const float*)d_in[10];
    const float* m3    = (const float*)d_in[11];
    const float* v3    = (const float*)d_in[12];
    const float* w2    = (const float*)d_in[13];
    const float* g2    = (const float*)d_in[14];
    const float* b2    = (const float*)d_in[15];
    const float* m2    = (const float*)d_in[16];
    const float* v2    = (const float*)d_in[17];
    float* out = (float*)d_out;

    const int smemD = 194304;   // deform: val + coeffs + wsm
    const int smem5 = (4224 + 5120 + 128) * 4;   // 37,888
    const int smem3 = (2 * 4 * 18 * 10 + 4 * 9 * 64 + 128) * 4;  // 15,488
    static bool attr_set = false;
    if (!attr_set) {
        cudaFuncSetAttribute(deform_mma_kernel,
                             cudaFuncAttributeMaxDynamicSharedMemorySize, smemD);
        cudaFuncSetAttribute(conv5_mma_kernel,
                             cudaFuncAttributeMaxDynamicSharedMemorySize, smem5);
        cudaFuncSetAttribute(conv3_final_kernel,
                             cudaFuncAttributeMaxDynamicSharedMemorySize, smem3);
        attr_set = true;
    }

    transpose_kernel<<<dim3(64, 16), 256>>>(x);
    offset_conv_kernel<<<dim3(16, 16), 256>>>(x, w_off, b_off);
    repack_wpk1_kernel<<<144, 256>>>(w1);
    repack_wpk5_kernel<<<400, 256>>>(w3);
    deform_mma_kernel<<<dim3(64, 16), 256, smemD>>>(g1, b1, m1, v1);
    conv5_mma_kernel<<<dim3(32, 16), 256, smem5>>>(x, g3, b3, m3, v3);
    conv3_final_kernel<<<dim3(32, 16), 256, smem3>>>(w2, g2, b2, m2, v2, x, out);
}

// round 7
// speedup vs baseline: 2.7201x; 1.4779x over previous
#include <cuda_runtime.h>

#define HW 4096
typedef unsigned long long ull;

__device__ float g_off[16 * 18 * HW];      // offsets from offset conv
__device__ float g_s[16 * 64 * HW];        // branch-sum feature map
__device__ float g_xt[16 * 64 * HW];       // x transposed to NHWC [b][y][x][c]
__device__ unsigned g_wpk5[102400];        // w3 fragment-packed (tf32 bits)
__device__ unsigned g_wpk1[36864];         // w1 fragment-packed (tf32 bits)
__device__ unsigned g_wpk3[36864];         // w2 fragment-packed (tf32 bits)
__device__ unsigned g_wpko[18432];         // w_off fragment-packed, oc padded to 32

// ---- tf32 mma helpers ------------------------------------------------------
__device__ __forceinline__ unsigned f2tf(float f) {
    unsigned u;
    asm("cvt.rna.tf32.f32 %0, %1;" : "=r"(u) : "f"(f));
    return u;
}
__device__ __forceinline__ void mma8(float* d, const unsigned* a, const unsigned* b) {
    asm("mma.sync.aligned.m16n8k8.row.col.f32.tf32.tf32.f32 "
        "{%0,%1,%2,%3},{%4,%5,%6,%7},{%8,%9},{%0,%1,%2,%3};"
        : "+f"(d[0]), "+f"(d[1]), "+f"(d[2]), "+f"(d[3])
        : "r"(a[0]), "r"(a[1]), "r"(a[2]), "r"(a[3]), "r"(b[0]), "r"(b[1]));
}

// ---------------------------------------------------------------------------
// Transpose x NCHW -> NHWC (g_xt)
// ---------------------------------------------------------------------------
__global__ __launch_bounds__(256) void transpose_kernel(const float* __restrict__ x)
{
    __shared__ float t[64][65];
    int tid = threadIdx.x;
    int y = blockIdx.x, b = blockIdx.y;
    const float* xb = x + (b * 64) * HW + y * 64;
#pragma unroll
    for (int i = 0; i < 16; i++) {
        int c = i * 4 + (tid >> 6), xc = tid & 63;
        t[xc][c] = xb[c * HW + xc];
    }
    __syncthreads();
    float* ob = g_xt + ((b * 64 + y) * 64) * 64;
#pragma unroll
    for (int i = 0; i < 16; i++) {
        int xc = i * 4 + (tid >> 6), c = tid & 63;
        ob[xc * 64 + c] = t[xc][c];
    }
}

// ---------------------------------------------------------------------------
// Weight repacks into mma A-fragment order (tf32-rounded)
// oc = strip*16 + l/4 + (r&1)*8 ; c within cblk: c8*8 + l%4 + (r>>1)*4
// ---------------------------------------------------------------------------
__global__ void repack_wpk5_kernel(const float* __restrict__ w3)
{
    int i = blockIdx.x * 256 + threadIdx.x;
    if (i < 102400) {
        int r = i & 3, lane = (i >> 2) & 31, strip = (i >> 7) & 3;
        int c8 = (i >> 9) & 1, cblk = (i >> 10) & 3, tap = i >> 12;
        int oc = strip * 16 + (lane >> 2) + (r & 1) * 8;
        int c  = cblk * 16 + c8 * 8 + (lane & 3) + (r >> 1) * 4;
        g_wpk5[i] = f2tf(w3[(oc * 64 + c) * 25 + tap]);
    }
}
__global__ void repack_wpk1_kernel(const float* __restrict__ w1)
{
    int i = blockIdx.x * 256 + threadIdx.x;
    if (i < 36864) {
        int r = i & 3, lane = (i >> 2) & 31, strip = (i >> 7) & 3, kstep = i >> 9;
        int oc = strip * 16 + (lane >> 2) + (r & 1) * 8;
        int K  = kstep * 8 + (lane & 3) + (r >> 1) * 4;
        int tap = K >> 6, c = K & 63;
        g_wpk1[i] = f2tf(w1[(oc * 64 + c) * 9 + tap]);
    }
}
__global__ void repack_wpk3_kernel(const float* __restrict__ w2)
{
    int i = blockIdx.x * 256 + threadIdx.x;
    if (i < 36864) {
        int r = i & 3, lane = (i >> 2) & 31, strip = (i >> 7) & 3;
        int c8 = (i >> 9) & 1, cblk = (i >> 10) & 3, tap = i >> 12;
        int oc = strip * 16 + (lane >> 2) + (r & 1) * 8;
        int c  = cblk * 16 + c8 * 8 + (lane & 3) + (r >> 1) * 4;
        g_wpk3[i] = f2tf(w2[(oc * 64 + c) * 9 + tap]);
    }
}
__global__ void repack_wpko_kernel(const float* __restrict__ w_off)
{
    int i = blockIdx.x * 256 + threadIdx.x;
    if (i < 18432) {
        int r = i & 3, lane = (i >> 2) & 31, strip = (i >> 7) & 1;
        int c8 = (i >> 8) & 1, cblk = (i >> 9) & 3, tap = i >> 11;
        int oc = strip * 16 + (lane >> 2) + (r & 1) * 8;
        int c  = cblk * 16 + c8 * 8 + (lane & 3) + (r >> 1) * 4;
        g_wpko[i] = (oc < 18) ? f2tf(w_off[(oc * 64 + c) * 9 + tap]) : 0u;
    }
}

// ---------------------------------------------------------------------------
// Offset conv as tf32 MMA implicit GEMM: 3x3 pad 1, Cout 18 (padded 32)
// Block: 8 rows x 16 cols. Warp -> 1 output row. 2 oc strips.
// ---------------------------------------------------------------------------
__global__ __launch_bounds__(256) void offset_mma_kernel(
    const float* __restrict__ x, const float* __restrict__ b_off)
{
    extern __shared__ unsigned om[];
    unsigned* xs  = om;            // [16 c][10 y][20 x] = 3200
    unsigned* wfr = om + 3200;     // [3 kx][2 c8][2 strip][128] = 1536

    int tid = threadIdx.x;
    int l   = tid & 31, wp = tid >> 5;
    int b   = blockIdx.y;
    int by0 = (blockIdx.x >> 2) * 8;
    int bx0 = (blockIdx.x & 3) * 16;

    float acc[2][2][4];
#pragma unroll
    for (int s = 0; s < 2; s++)
#pragma unroll
        for (int g = 0; g < 2; g++)
#pragma unroll
            for (int r = 0; r < 4; r++) acc[s][g][r] = 0.f;

    const unsigned* bbase = xs + (l & 3) * 200 + wp * 20 + (l >> 2);

    for (int cblk = 0; cblk < 4; cblk++) {
        __syncthreads();
        for (int i = tid; i < 2880; i += 256) {
            int c = i / 180, rr = i % 180, yy = rr / 18, xx = rr % 18;
            int gy = by0 - 1 + yy, gx = bx0 - 1 + xx;
            float v = 0.f;
            if (gy >= 0 && gy < 64 && gx >= 0 && gx < 64)
                v = x[((b * 64 + cblk * 16 + c) * 64 + gy) * 64 + gx];
            xs[(c * 10 + yy) * 20 + xx] = f2tf(v);
        }
        for (int ky = 0; ky < 3; ky++) {
            __syncthreads();
            for (int i4 = tid; i4 < 384; i4 += 256) {
                int tl = i4 >> 7, rest = i4 & 127;
                ((uint4*)wfr)[i4] =
                    ((const uint4*)(g_wpko + (ky * 3 + tl) * 2048 + cblk * 512))[rest];
            }
            __syncthreads();
#pragma unroll
            for (int kx = 0; kx < 3; kx++) {
#pragma unroll
                for (int c8 = 0; c8 < 2; c8++) {
                    unsigned A[2][4];
#pragma unroll
                    for (int s = 0; s < 2; s++)
                        *(uint4*)A[s] = *(const uint4*)(wfr + (kx * 2 + c8) * 256 + s * 128 + l * 4);
#pragma unroll
                    for (int g = 0; g < 2; g++) {
                        unsigned bf[2];
                        bf[0] = bbase[c8 * 1600 + ky * 20 + g * 8 + kx];
                        bf[1] = bbase[c8 * 1600 + 800 + ky * 20 + g * 8 + kx];
#pragma unroll
                        for (int s = 0; s < 2; s++) mma8(acc[s][g], A[s], bf);
                    }
                }
            }
        }
    }

    int row_g = by0 + wp;
#pragma unroll
    for (int s = 0; s < 2; s++) {
#pragma unroll
        for (int g = 0; g < 2; g++) {
            int oc0 = s * 16 + (l >> 2);
            int oc1 = oc0 + 8;
            int col = bx0 + g * 8 + (l & 3) * 2;
            if (oc0 < 18) {
                float bi = b_off[oc0];
                float* o = &g_off[((b * 18 + oc0) * 64 + row_g) * 64 + col];
                o[0] = acc[s][g][0] + bi;
                o[1] = acc[s][g][1] + bi;
            }
            if (oc1 < 18) {
                float bi = b_off[oc1];
                float* o = &g_off[((b * 18 + oc1) * 64 + row_g) * 64 + col];
                o[0] = acc[s][g][2] + bi;
                o[1] = acc[s][g][3] + bi;
            }
        }
    }
}

// ---------------------------------------------------------------------------
// Deformable conv (3x3, pad 1) + BN1 + ReLU -> g_s, tf32 mma GEMM
// ---------------------------------------------------------------------------
__global__ __launch_bounds__(256) void deform_mma_kernel(
    const float* __restrict__ g1, const float* __restrict__ b1,
    const float* __restrict__ m1, const float* __restrict__ v1)
{
    extern __shared__ unsigned dm[];
    unsigned* val = dm;                          // [576][72]
    float* cw00   = (float*)(dm + 41472);        // [576]
    float* cw01   = cw00 + 576;
    float* cw10   = cw01 + 576;
    float* cw11   = cw10 + 576;
    int*   cpos   = (int*)(cw11 + 576);          // [576]
    float* scale  = (float*)(cpos + 576);        // [64]
    float* bias   = scale + 64;                  // [64]
    unsigned* wsm = (unsigned*)(bias + 64);      // [4096]

    int tid = threadIdx.x;
    int l   = tid & 31, wp = tid >> 5;
    int ho  = blockIdx.x, b = blockIdx.y;

    if (tid < 64) {
        float sc   = g1[tid] * rsqrtf(v1[tid] + 1e-5f);
        scale[tid] = sc;
        bias[tid]  = b1[tid] - m1[tid] * sc;
    }
    for (int t = tid; t < 576; t += 256) {
        int k = t >> 6, px = t & 63;
        int ky = k / 3, kx = k % 3;
        int wo = px;
        float dy = g_off[((b * 18 + 2 * k) * 64 + ho) * 64 + wo];
        float dx = g_off[((b * 18 + 2 * k + 1) * 64 + ho) * 64 + wo];
        float ys  = (float)(ho - 1 + ky) + dy;
        float xsm = (float)(wo - 1 + kx) + dx;
        float y0f = floorf(ys), x0f = floorf(xsm);
        float y1f = y0f + 1.f, x1f = x0f + 1.f;
        float wy1 = ys - y0f, wx1 = xsm - x0f;
        float wy0 = 1.f - wy1, wx0 = 1.f - wx1;
        bool vy0 = (y0f >= 0.f) && (y0f <= 63.f);
        bool vy1 = (y1f >= 0.f) && (y1f <= 63.f);
        bool vx0 = (x0f >= 0.f) && (x0f <= 63.f);
        bool vx1 = (x1f >= 0.f) && (x1f <= 63.f);
        cw00[t] = (vy0 && vx0) ? wy0 * wx0 : 0.f;
        cw01[t] = (vy0 && vx1) ? wy0 * wx1 : 0.f;
        cw10[t] = (vy1 && vx0) ? wy1 * wx0 : 0.f;
        cw11[t] = (vy1 && vx1) ? wy1 * wx1 : 0.f;
        int y0c = (int)fminf(fmaxf(y0f, 0.f), 63.f);
        int x0c = (int)fminf(fmaxf(x0f, 0.f), 63.f);
        int y1c = (int)fminf(fmaxf(y1f, 0.f), 63.f);
        int x1c = (int)fminf(fmaxf(x1f, 0.f), 63.f);
        cpos[t] = y0c | (x0c << 6) | (y1c << 12) | (x1c << 18);
    }
    __syncthreads();

    for (int it = 0; it < 9; it++) {
        int t  = tid + it * 256;
        int cg = t & 3, px = (t >> 2) & 63, k = t >> 8;
        int pair = k * 64 + px;
        int p  = cpos[pair];
        float w00 = cw00[pair], w01 = cw01[pair];
        float w10 = cw10[pair], w11 = cw11[pair];
        int y0 = p & 63, x0 = (p >> 6) & 63;
        int y1 = (p >> 12) & 63, x1 = (p >> 18) & 63;
        const float4* p00 = (const float4*)(g_xt + (((b * 64 + y0) * 64 + x0) * 64) + cg * 16);
        const float4* p01 = (const float4*)(g_xt + (((b * 64 + y0) * 64 + x1) * 64) + cg * 16);
        const float4* p10 = (const float4*)(g_xt + (((b * 64 + y1) * 64 + x0) * 64) + cg * 16);
        const float4* p11 = (const float4*)(g_xt + (((b * 64 + y1) * 64 + x1) * 64) + cg * 16);
        unsigned* vout = val + (k * 64 + cg * 16) * 72 + px;
#pragma unroll
        for (int i = 0; i < 4; i++) {
            float4 a = p00[i], bq = p01[i], cq = p10[i], dq = p11[i];
            float r0 = w00 * a.x + w01 * bq.x + w10 * cq.x + w11 * dq.x;
            float r1 = w00 * a.y + w01 * bq.y + w10 * cq.y + w11 * dq.y;
            float r2 = w00 * a.z + w01 * bq.z + w10 * cq.z + w11 * dq.z;
            float r3 = w00 * a.w + w01 * bq.w + w10 * cq.w + w11 * dq.w;
            vout[(i * 4 + 0) * 72] = f2tf(r0);
            vout[(i * 4 + 1) * 72] = f2tf(r1);
            vout[(i * 4 + 2) * 72] = f2tf(r2);
            vout[(i * 4 + 3) * 72] = f2tf(r3);
        }
    }
    __syncthreads();

    float acc[4][4];
#pragma unroll
    for (int s = 0; s < 4; s++)
#pragma unroll
        for (int r = 0; r < 4; r++) acc[s][r] = 0.f;

    const unsigned* vb = val + (l & 3) * 72 + wp * 8 + (l >> 2);

    for (int kc = 0; kc < 9; kc++) {
        __syncthreads();
        for (int i4 = tid; i4 < 1024; i4 += 256)
            ((uint4*)wsm)[i4] = ((const uint4*)(g_wpk1 + kc * 4096))[i4];
        __syncthreads();
#pragma unroll
        for (int ks = 0; ks < 8; ks++) {
            int kstep = kc * 8 + ks;
            unsigned A[4][4];
#pragma unroll
            for (int s = 0; s < 4; s++)
                *(uint4*)A[s] = *(const uint4*)(wsm + (ks * 4 + s) * 128 + l * 4);
            unsigned bf[2];
            bf[0] = vb[kstep * 576];
            bf[1] = vb[kstep * 576 + 288];
#pragma unroll
            for (int s = 0; s < 4; s++) mma8(acc[s], A[s], bf);
        }
    }

    int col = wp * 8 + (l & 3) * 2;
#pragma unroll
    for (int s = 0; s < 4; s++) {
        int oc0 = s * 16 + (l >> 2);
        int oc1 = oc0 + 8;
        float sc0 = scale[oc0], bi0 = bias[oc0];
        float sc1 = scale[oc1], bi1 = bias[oc1];
        float2 v0 = make_float2(fmaxf(acc[s][0] * sc0 + bi0, 0.f),
                                fmaxf(acc[s][1] * sc0 + bi0, 0.f));
        float2 v1 = make_float2(fmaxf(acc[s][2] * sc1 + bi1, 0.f),
                                fmaxf(acc[s][3] * sc1 + bi1, 0.f));
        *(float2*)&g_s[((b * 64 + oc0) * 64 + ho) * 64 + col] = v0;
        *(float2*)&g_s[((b * 64 + oc1) * 64 + ho) * 64 + col] = v1;
    }
}

// ---------------------------------------------------------------------------
// conv5 (5x5, pad 2) + BN3 + ReLU, accumulated into g_s — tf32 mma
// ---------------------------------------------------------------------------
__global__ __launch_bounds__(256) void conv5_mma_kernel(
    const float* __restrict__ x,
    const float* __restrict__ gg, const float* __restrict__ bbn,
    const float* __restrict__ mmn, const float* __restrict__ vvn)
{
    extern __shared__ unsigned cm[];
    unsigned* xs  = cm;                      // [16][12][22]
    unsigned* wfr = cm + 4224;               // [5 kx][2 c8][4 strip][128]
    float* scale  = (float*)(cm + 4224 + 5120);
    float* bias   = scale + 64;

    int tid = threadIdx.x;
    int l   = tid & 31, wp = tid >> 5;
    int b   = blockIdx.y;
    int by0 = (blockIdx.x >> 2) * 8;
    int bx0 = (blockIdx.x & 3) * 16;

    if (tid < 64) {
        float sc   = gg[tid] * rsqrtf(vvn[tid] + 1e-5f);
        scale[tid] = sc;
        bias[tid]  = bbn[tid] - mmn[tid] * sc;
    }

    float acc[4][2][4];
#pragma unroll
    for (int s = 0; s < 4; s++)
#pragma unroll
        for (int g = 0; g < 2; g++)
#pragma unroll
            for (int r = 0; r < 4; r++) acc[s][g][r] = 0.f;

    const unsigned* bbase = xs + (l & 3) * 264 + wp * 22 + (l >> 2);

    for (int cblk = 0; cblk < 4; cblk++) {
        __syncthreads();
        for (int i = tid; i < 3840; i += 256) {
            int c = i / 240, rr = i % 240, yy = rr / 20, xx = rr % 20;
            int gy = by0 - 2 + yy, gx = bx0 - 2 + xx;
            float v = 0.f;
            if (gy >= 0 && gy < 64 && gx >= 0 && gx < 64)
                v = x[((b * 64 + cblk * 16 + c) * 64 + gy) * 64 + gx];
            xs[(c * 12 + yy) * 22 + xx] = f2tf(v);
        }
        for (int ky = 0; ky < 5; ky++) {
            __syncthreads();
            for (int i4 = tid; i4 < 1280; i4 += 256) {
                int tl = i4 >> 8, rest = i4 & 255;
                ((uint4*)wfr)[i4] =
                    ((const uint4*)(g_wpk5 + (ky * 5 + tl) * 4096 + cblk * 1024))[rest];
            }
            __syncthreads();
#pragma unroll
            for (int kx = 0; kx < 5; kx++) {
#pragma unroll
                for (int c8 = 0; c8 < 2; c8++) {
                    unsigned A[4][4];
#pragma unroll
                    for (int s = 0; s < 4; s++)
                        *(uint4*)A[s] = *(const uint4*)(wfr + (kx * 2 + c8) * 512 + s * 128 + l * 4);
#pragma unroll
                    for (int g = 0; g < 2; g++) {
                        unsigned bf[2];
                        bf[0] = bbase[c8 * 2112 + ky * 22 + g * 8 + kx];
                        bf[1] = bbase[c8 * 2112 + 1056 + ky * 22 + g * 8 + kx];
#pragma unroll
                        for (int s = 0; s < 4; s++) mma8(acc[s][g], A[s], bf);
                    }
                }
            }
        }
    }

    int row_g = by0 + wp;
#pragma unroll
    for (int s = 0; s < 4; s++) {
#pragma unroll
        for (int g = 0; g < 2; g++) {
            int oc0 = s * 16 + (l >> 2);
            int oc1 = oc0 + 8;
            int col = bx0 + g * 8 + (l & 3) * 2;
            float sc0 = scale[oc0], bi0 = bias[oc0];
            float sc1 = scale[oc1], bi1 = bias[oc1];
            float* a0 = &g_s[((b * 64 + oc0) * 64 + row_g) * 64 + col];
            float* a1 = &g_s[((b * 64 + oc1) * 64 + row_g) * 64 + col];
            float2 o0 = *(float2*)a0;
            float2 o1 = *(float2*)a1;
            o0.x += fmaxf(acc[s][g][0] * sc0 + bi0, 0.f);
            o0.y += fmaxf(acc[s][g][1] * sc0 + bi0, 0.f);
            o1.x += fmaxf(acc[s][g][2] * sc1 + bi1, 0.f);
            o1.y += fmaxf(acc[s][g][3] * sc1 + bi1, 0.f);
            *(float2*)a0 = o0;
            *(float2*)a1 = o1;
        }
    }
}

// ---------------------------------------------------------------------------
// Final conv: 3x3, pad 1, on g_s, + BN2 + residual + ReLU -> dst — tf32 mma
// Row stride 20 so channel plane (200) ≡ 8 mod 32 -> conflict-free B frags.
// ---------------------------------------------------------------------------
__global__ __launch_bounds__(256) void conv3_mma_kernel(
    const float* __restrict__ gg, const float* __restrict__ bbn,
    const float* __restrict__ mmn, const float* __restrict__ vvn,
    const float* __restrict__ resid, float* __restrict__ dst)
{
    extern __shared__ unsigned c3[];
    unsigned* xs  = c3;                      // [16 c][10 y][20 x] = 3200
    unsigned* wfr = c3 + 3200;               // [3 kx][2 c8][4 strip][128] = 3072
    float* scale  = (float*)(c3 + 3200 + 3072);
    float* bias   = scale + 64;

    int tid = threadIdx.x;
    int l   = tid & 31, wp = tid >> 5;
    int b   = blockIdx.y;
    int by0 = (blockIdx.x >> 2) * 8;
    int bx0 = (blockIdx.x & 3) * 16;

    if (tid < 64) {
        float sc   = gg[tid] * rsqrtf(vvn[tid] + 1e-5f);
        scale[tid] = sc;
        bias[tid]  = bbn[tid] - mmn[tid] * sc;
    }

    float acc[4][2][4];
#pragma unroll
    for (int s = 0; s < 4; s++)
#pragma unroll
        for (int g = 0; g < 2; g++)
#pragma unroll
            for (int r = 0; r < 4; r++) acc[s][g][r] = 0.f;

    const unsigned* bbase = xs + (l & 3) * 200 + wp * 20 + (l >> 2);

    for (int cblk = 0; cblk < 4; cblk++) {
        __syncthreads();
        for (int i = tid; i < 2880; i += 256) {
            int c = i / 180, rr = i % 180, yy = rr / 18, xx = rr % 18;
            int gy = by0 - 1 + yy, gx = bx0 - 1 + xx;
            float v = 0.f;
            if (gy >= 0 && gy < 64 && gx >= 0 && gx < 64)
                v = g_s[((b * 64 + cblk * 16 + c) * 64 + gy) * 64 + gx];
            xs[(c * 10 + yy) * 20 + xx] = f2tf(v);
        }
        for (int ky = 0; ky < 3; ky++) {
            __syncthreads();
            for (int i4 = tid; i4 < 768; i4 += 256) {
                int tl = i4 >> 8, rest = i4 & 255;
                ((uint4*)wfr)[i4] =
                    ((const uint4*)(g_wpk3 + (ky * 3 + tl) * 4096 + cblk * 1024))[rest];
            }
            __syncthreads();
#pragma unroll
            for (int kx = 0; kx < 3; kx++) {
#pragma unroll
                for (int c8 = 0; c8 < 2; c8++) {
                    unsigned A[4][4];
#pragma unroll
                    for (int s = 0; s < 4; s++)
                        *(uint4*)A[s] = *(const uint4*)(wfr + (kx * 2 + c8) * 512 + s * 128 + l * 4);
#pragma unroll
                    for (int g = 0; g < 2; g++) {
                        unsigned bf[2];
                        bf[0] = bbase[c8 * 1600 + ky * 20 + g * 8 + kx];
                        bf[1] = bbase[c8 * 1600 + 800 + ky * 20 + g * 8 + kx];
#pragma unroll
                        for (int s = 0; s < 4; s++) mma8(acc[s][g], A[s], bf);
                    }
                }
            }
        }
    }

    int row_g = by0 + wp;
#pragma unroll
    for (int s = 0; s < 4; s++) {
#pragma unroll
        for (int g = 0; g < 2; g++) {
            int oc0 = s * 16 + (l >> 2);
            int oc1 = oc0 + 8;
            int col = bx0 + g * 8 + (l & 3) * 2;
            float sc0 = scale[oc0], bi0 = bias[oc0];
            float sc1 = scale[oc1], bi1 = bias[oc1];
            int i0 = ((b * 64 + oc0) * 64 + row_g) * 64 + col;
            int i1 = ((b * 64 + oc1) * 64 + row_g) * 64 + col;
            float2 r0 = *(const float2*)&resid[i0];
            float2 r1 = *(const float2*)&resid[i1];
            float2 o0 = make_float2(
                fmaxf(acc[s][g][0] * sc0 + bi0 + r0.x, 0.f),
                fmaxf(acc[s][g][1] * sc0 + bi0 + r0.y, 0.f));
            float2 o1 = make_float2(
                fmaxf(acc[s][g][2] * sc1 + bi1 + r1.x, 0.f),
                fmaxf(acc[s][g][3] * sc1 + bi1 + r1.y, 0.f));
            *(float2*)&dst[i0] = o0;
            *(float2*)&dst[i1] = o1;
        }
    }
}

// ---------------------------------------------------------------------------
extern "C" void kernel_launch(void* const* d_in, const int* in_sizes, int n_in,
                              void* d_out, int out_size)
{
    const float* x     = (const float*)d_in[0];
    const float* w_off = (const float*)d_in[1];
    const float* b_off = (const float*)d_in[2];
    const float* w1    = (const float*)d_in[3];
    const float* g1    = (const float*)d_in[4];
    const float* b1    = (const float*)d_in[5];
    const float* m1    = (const float*)d_in[6];
    const float* v1    = (const float*)d_in[7];
    const float* w3    = (const float*)d_in[8];
    const float* g3    = (const float*)d_in[9];
    const float* b3    = (const float*)d_in[10];
    const float* m3    = (const float*)d_in[11];
    const float* v3    = (const float*)d_in[12];
    const float* w2    = (const float*)d_in[13];
    const float* g2    = (const float*)d_in[14];
    const float* b2    = (const float*)d_in[15];
    const float* m2    = (const float*)d_in[16];
    const float* v2    = (const float*)d_in[17];
    float* out = (float*)d_out;

    const int smemD = 194304;                       // deform
    const int smem5 = (4224 + 5120 + 128) * 4;      // 37,888
    const int smem3 = (3200 + 3072 + 128) * 4;      // 25,600
    const int smemO = (3200 + 1536) * 4;            // 18,944
    static bool attr_set = false;
    if (!attr_set) {
        cudaFuncSetAttribute(deform_mma_kernel,
                             cudaFuncAttributeMaxDynamicSharedMemorySize, smemD);
        cudaFuncSetAttribute(conv5_mma_kernel,
                             cudaFuncAttributeMaxDynamicSharedMemorySize, smem5);
        cudaFuncSetAttribute(conv3_mma_kernel,
                             cudaFuncAttributeMaxDynamicSharedMemorySize, smem3);
        cudaFuncSetAttribute(offset_mma_kernel,
                             cudaFuncAttributeMaxDynamicSharedMemorySize, smemO);
        attr_set = true;
    }

    transpose_kernel<<<dim3(64, 16), 256>>>(x);
    repack_wpko_kernel<<<72, 256>>>(w_off);
    repack_wpk1_kernel<<<144, 256>>>(w1);
    repack_wpk5_kernel<<<400, 256>>>(w3);
    repack_wpk3_kernel<<<144, 256>>>(w2);
    offset_mma_kernel<<<dim3(32, 16), 256, smemO>>>(x, b_off);
    deform_mma_kernel<<<dim3(64, 16), 256, smemD>>>(g1, b1, m1, v1);
    conv5_mma_kernel<<<dim3(32, 16), 256, smem5>>>(x, g3, b3, m3, v3);
    conv3_mma_kernel<<<dim3(32, 16), 256, smem3>>>(g2, b2, m2, v2, x, out);
}

// round 8
// speedup vs baseline: 3.3734x; 1.2402x over previous
#include <cuda_runtime.h>
#include <cuda_fp16.h>

#define HW 4096
typedef unsigned long long ull;

__device__ float  g_off[16 * 18 * HW];     // offsets from offset conv
__device__ float  g_s[16 * 64 * HW];       // branch-sum feature map
__device__ __half g_xth[16 * 64 * HW];     // x transposed to NHWC fp16
__device__ unsigned g_wpk5[102400];        // w3 fragment-packed (tf32 bits)
__device__ unsigned g_wpk1[36864];         // w1 fragment-packed
__device__ unsigned g_wpk3[36864];         // w2 fragment-packed
__device__ unsigned g_wpko[18432];         // w_off fragment-packed (oc pad 32)

// ---- tf32 mma helpers ------------------------------------------------------
__device__ __forceinline__ unsigned f2tf(float f) {
    unsigned u;
    asm("cvt.rna.tf32.f32 %0, %1;" : "=r"(u) : "f"(f));
    return u;
}
__device__ __forceinline__ void mma8(float* d, const unsigned* a, const unsigned* b) {
    asm("mma.sync.aligned.m16n8k8.row.col.f32.tf32.tf32.f32 "
        "{%0,%1,%2,%3},{%4,%5,%6,%7},{%8,%9},{%0,%1,%2,%3};"
        : "+f"(d[0]), "+f"(d[1]), "+f"(d[2]), "+f"(d[3])
        : "r"(a[0]), "r"(a[1]), "r"(a[2]), "r"(a[3]), "r"(b[0]), "r"(b[1]));
}

// ---------------------------------------------------------------------------
// Transpose x NCHW -> NHWC fp16 (g_xth)
// ---------------------------------------------------------------------------
__global__ __launch_bounds__(256) void transpose_kernel(const float* __restrict__ x)
{
    __shared__ float t[64][65];
    int tid = threadIdx.x;
    int y = blockIdx.x, b = blockIdx.y;
    const float* xb = x + (b * 64) * HW + y * 64;
#pragma unroll
    for (int i = 0; i < 16; i++) {
        int c = i * 4 + (tid >> 6), xc = tid & 63;
        t[xc][c] = xb[c * HW + xc];
    }
    __syncthreads();
    __half* ob = g_xth + ((b * 64 + y) * 64) * 64;
#pragma unroll
    for (int i = 0; i < 16; i++) {
        int xc = i * 4 + (tid >> 6), c = tid & 63;
        ob[xc * 64 + c] = __float2half(t[xc][c]);
    }
}

// ---------------------------------------------------------------------------
// All weight repacks in ONE kernel (tf32-rounded, mma A-fragment order)
// ---------------------------------------------------------------------------
__global__ void repack_all_kernel(const float* __restrict__ w3,
                                  const float* __restrict__ w1,
                                  const float* __restrict__ w2,
                                  const float* __restrict__ w_off)
{
    int i = blockIdx.x * 256 + threadIdx.x;
    if (i < 102400) {
        int r = i & 3, lane = (i >> 2) & 31, strip = (i >> 7) & 3;
        int c8 = (i >> 9) & 1, cblk = (i >> 10) & 3, tap = i >> 12;
        int oc = strip * 16 + (lane >> 2) + (r & 1) * 8;
        int c  = cblk * 16 + c8 * 8 + (lane & 3) + (r >> 1) * 4;
        g_wpk5[i] = f2tf(w3[(oc * 64 + c) * 25 + tap]);
    } else if (i < 139264) {
        int j = i - 102400;
        int r = j & 3, lane = (j >> 2) & 31, strip = (j >> 7) & 3, kstep = j >> 9;
        int oc = strip * 16 + (lane >> 2) + (r & 1) * 8;
        int K  = kstep * 8 + (lane & 3) + (r >> 1) * 4;
        int tap = K >> 6, c = K & 63;
        g_wpk1[j] = f2tf(w1[(oc * 64 + c) * 9 + tap]);
    } else if (i < 176128) {
        int j = i - 139264;
        int r = j & 3, lane = (j >> 2) & 31, strip = (j >> 7) & 3;
        int c8 = (j >> 9) & 1, cblk = (j >> 10) & 3, tap = j >> 12;
        int oc = strip * 16 + (lane >> 2) + (r & 1) * 8;
        int c  = cblk * 16 + c8 * 8 + (lane & 3) + (r >> 1) * 4;
        g_wpk3[j] = f2tf(w2[(oc * 64 + c) * 9 + tap]);
    } else if (i < 194560) {
        int j = i - 176128;
        int r = j & 3, lane = (j >> 2) & 31, strip = (j >> 7) & 1;
        int c8 = (j >> 8) & 1, cblk = (j >> 9) & 3, tap = j >> 11;
        int oc = strip * 16 + (lane >> 2) + (r & 1) * 8;
        int c  = cblk * 16 + c8 * 8 + (lane & 3) + (r >> 1) * 4;
        g_wpko[j] = (oc < 18) ? f2tf(w_off[(oc * 64 + c) * 9 + tap]) : 0u;
    }
}

// ---------------------------------------------------------------------------
// Offset conv as tf32 MMA implicit GEMM: 3x3 pad 1, Cout 18 (padded 32)
// ---------------------------------------------------------------------------
__global__ __launch_bounds__(256) void offset_mma_kernel(
    const float* __restrict__ x, const float* __restrict__ b_off)
{
    extern __shared__ unsigned om[];
    unsigned* xs  = om;            // [16 c][10 y][20 x] = 3200
    unsigned* wfr = om + 3200;     // [3 kx][2 c8][2 strip][128] = 1536

    int tid = threadIdx.x;
    int l   = tid & 31, wp = tid >> 5;
    int b   = blockIdx.y;
    int by0 = (blockIdx.x >> 2) * 8;
    int bx0 = (blockIdx.x & 3) * 16;

    float acc[2][2][4];
#pragma unroll
    for (int s = 0; s < 2; s++)
#pragma unroll
        for (int g = 0; g < 2; g++)
#pragma unroll
            for (int r = 0; r < 4; r++) acc[s][g][r] = 0.f;

    const unsigned* bbase = xs + (l & 3) * 200 + wp * 20 + (l >> 2);

    for (int cblk = 0; cblk < 4; cblk++) {
        __syncthreads();
        for (int i = tid; i < 2880; i += 256) {
            int c = i / 180, rr = i % 180, yy = rr / 18, xx = rr % 18;
            int gy = by0 - 1 + yy, gx = bx0 - 1 + xx;
            float v = 0.f;
            if (gy >= 0 && gy < 64 && gx >= 0 && gx < 64)
                v = x[((b * 64 + cblk * 16 + c) * 64 + gy) * 64 + gx];
            xs[(c * 10 + yy) * 20 + xx] = f2tf(v);
        }
        for (int ky = 0; ky < 3; ky++) {
            __syncthreads();
            for (int i4 = tid; i4 < 384; i4 += 256) {
                int tl = i4 >> 7, rest = i4 & 127;
                ((uint4*)wfr)[i4] =
                    ((const uint4*)(g_wpko + (ky * 3 + tl) * 2048 + cblk * 512))[rest];
            }
            __syncthreads();
#pragma unroll
            for (int kx = 0; kx < 3; kx++) {
#pragma unroll
                for (int c8 = 0; c8 < 2; c8++) {
                    unsigned A[2][4];
#pragma unroll
                    for (int s = 0; s < 2; s++)
                        *(uint4*)A[s] = *(const uint4*)(wfr + (kx * 2 + c8) * 256 + s * 128 + l * 4);
#pragma unroll
                    for (int g = 0; g < 2; g++) {
                        unsigned bf[2];
                        bf[0] = bbase[c8 * 1600 + ky * 20 + g * 8 + kx];
                        bf[1] = bbase[c8 * 1600 + 800 + ky * 20 + g * 8 + kx];
#pragma unroll
                        for (int s = 0; s < 2; s++) mma8(acc[s][g], A[s], bf);
                    }
                }
            }
        }
    }

    int row_g = by0 + wp;
#pragma unroll
    for (int s = 0; s < 2; s++) {
#pragma unroll
        for (int g = 0; g < 2; g++) {
            int oc0 = s * 16 + (l >> 2);
            int oc1 = oc0 + 8;
            int col = bx0 + g * 8 + (l & 3) * 2;
            if (oc0 < 18) {
                float bi = b_off[oc0];
                float* o = &g_off[((b * 18 + oc0) * 64 + row_g) * 64 + col];
                o[0] = acc[s][g][0] + bi;
                o[1] = acc[s][g][1] + bi;
            }
            if (oc1 < 18) {
                float bi = b_off[oc1];
                float* o = &g_off[((b * 18 + oc1) * 64 + row_g) * 64 + col];
                o[0] = acc[s][g][2] + bi;
                o[1] = acc[s][g][3] + bi;
            }
        }
    }
}

// ---------------------------------------------------------------------------
// Deformable conv (3x3, pad 1) + BN1 + ReLU -> g_s, tf32 mma GEMM
// v3: fp16 NHWC gather (half traffic), K-chunked val (84KB smem, 2 CTA/SM)
// ---------------------------------------------------------------------------
__global__ __launch_bounds__(256) void deform_mma_kernel(
    const float* __restrict__ g1, const float* __restrict__ b1,
    const float* __restrict__ m1, const float* __restrict__ v1)
{
    extern __shared__ unsigned dm[];
    unsigned* val = dm;                          // [192][72] (chunk of 3 taps)
    float* cw00   = (float*)(dm + 13824);        // [576]
    float* cw01   = cw00 + 576;
    float* cw10   = cw01 + 576;
    float* cw11   = cw10 + 576;
    int*   cpos   = (int*)(cw11 + 576);          // [576]
    float* scale  = (float*)(cpos + 576);        // [64]
    float* bias   = scale + 64;                  // [64]
    unsigned* wsm = (unsigned*)(bias + 64);      // [4096]

    int tid = threadIdx.x;
    int l   = tid & 31, wp = tid >> 5;
    int ho  = blockIdx.x, b = blockIdx.y;

    if (tid < 64) {
        float sc   = g1[tid] * rsqrtf(v1[tid] + 1e-5f);
        scale[tid] = sc;
        bias[tid]  = b1[tid] - m1[tid] * sc;
    }
    for (int t = tid; t < 576; t += 256) {
        int k = t >> 6, px = t & 63;
        int ky = k / 3, kx = k % 3;
        int wo = px;
        float dy = g_off[((b * 18 + 2 * k) * 64 + ho) * 64 + wo];
        float dx = g_off[((b * 18 + 2 * k + 1) * 64 + ho) * 64 + wo];
        float ys  = (float)(ho - 1 + ky) + dy;
        float xsm = (float)(wo - 1 + kx) + dx;
        float y0f = floorf(ys), x0f = floorf(xsm);
        float y1f = y0f + 1.f, x1f = x0f + 1.f;
        float wy1 = ys - y0f, wx1 = xsm - x0f;
        float wy0 = 1.f - wy1, wx0 = 1.f - wx1;
        bool vy0 = (y0f >= 0.f) && (y0f <= 63.f);
        bool vy1 = (y1f >= 0.f) && (y1f <= 63.f);
        bool vx0 = (x0f >= 0.f) && (x0f <= 63.f);
        bool vx1 = (x1f >= 0.f) && (x1f <= 63.f);
        cw00[t] = (vy0 && vx0) ? wy0 * wx0 : 0.f;
        cw01[t] = (vy0 && vx1) ? wy0 * wx1 : 0.f;
        cw10[t] = (vy1 && vx0) ? wy1 * wx0 : 0.f;
        cw11[t] = (vy1 && vx1) ? wy1 * wx1 : 0.f;
        int y0c = (int)fminf(fmaxf(y0f, 0.f), 63.f);
        int x0c = (int)fminf(fmaxf(x0f, 0.f), 63.f);
        int y1c = (int)fminf(fmaxf(y1f, 0.f), 63.f);
        int x1c = (int)fminf(fmaxf(x1f, 0.f), 63.f);
        cpos[t] = y0c | (x0c << 6) | (y1c << 12) | (x1c << 18);
    }

    float acc[4][4];
#pragma unroll
    for (int s = 0; s < 4; s++)
#pragma unroll
        for (int r = 0; r < 4; r++) acc[s][r] = 0.f;

    const unsigned* vb = val + (l & 3) * 72 + wp * 8 + (l >> 2);

    for (int kc3 = 0; kc3 < 3; kc3++) {
        __syncthreads();   // val + coeffs ready / prev GEMM done reading val

        // gather this chunk (taps 3*kc3 .. 3*kc3+2): 768 tasks
#pragma unroll
        for (int it = 0; it < 3; it++) {
            int t  = tid + it * 256;
            int cg = t & 3, px = (t >> 2) & 63, kt = t >> 8;
            int pair = (kc3 * 3 + kt) * 64 + px;
            int p  = cpos[pair];
            float w00 = cw00[pair], w01 = cw01[pair];
            float w10 = cw10[pair], w11 = cw11[pair];
            int y0 = p & 63, x0 = (p >> 6) & 63;
            int y1 = (p >> 12) & 63, x1 = (p >> 18) & 63;
            const uint4* p00 = (const uint4*)(g_xth + (((b * 64 + y0) * 64 + x0) * 64) + cg * 16);
            const uint4* p01 = (const uint4*)(g_xth + (((b * 64 + y0) * 64 + x1) * 64) + cg * 16);
            const uint4* p10 = (const uint4*)(g_xth + (((b * 64 + y1) * 64 + x0) * 64) + cg * 16);
            const uint4* p11 = (const uint4*)(g_xth + (((b * 64 + y1) * 64 + x1) * 64) + cg * 16);
            unsigned* vout = val + (kt * 64 + cg * 16) * 72 + px;
#pragma unroll
            for (int h = 0; h < 2; h++) {
                uint4 q00 = p00[h], q01 = p01[h], q10 = p10[h], q11 = p11[h];
                const __half2* h00 = (const __half2*)&q00;
                const __half2* h01 = (const __half2*)&q01;
                const __half2* h10 = (const __half2*)&q10;
                const __half2* h11 = (const __half2*)&q11;
#pragma unroll
                for (int j = 0; j < 4; j++) {
                    float2 c00 = __half22float2(h00[j]);
                    float2 c01 = __half22float2(h01[j]);
                    float2 c10 = __half22float2(h10[j]);
                    float2 c11 = __half22float2(h11[j]);
                    float r0 = w00 * c00.x + w01 * c01.x + w10 * c10.x + w11 * c11.x;
                    float r1 = w00 * c00.y + w01 * c01.y + w10 * c10.y + w11 * c11.y;
                    int cc = h * 8 + j * 2;
                    vout[cc * 72]       = f2tf(r0);
                    vout[(cc + 1) * 72] = f2tf(r1);
                }
            }
        }
        __syncthreads();   // gather complete

        for (int tap = 0; tap < 3; tap++) {
            int kc = kc3 * 3 + tap;
            if (tap) __syncthreads();   // prev wsm readers done
            for (int i4 = tid; i4 < 1024; i4 += 256)
                ((uint4*)wsm)[i4] = ((const uint4*)(g_wpk1 + kc * 4096))[i4];
            __syncthreads();
#pragma unroll
            for (int ks = 0; ks < 8; ks++) {
                int klocal = tap * 8 + ks;
                unsigned A[4][4];
#pragma unroll
                for (int s = 0; s < 4; s++)
                    *(uint4*)A[s] = *(const uint4*)(wsm + (ks * 4 + s) * 128 + l * 4);
                unsigned bf[2];
                bf[0] = vb[klocal * 576];
                bf[1] = vb[klocal * 576 + 288];
#pragma unroll
                for (int s = 0; s < 4; s++) mma8(acc[s], A[s], bf);
            }
        }
    }

    int col = wp * 8 + (l & 3) * 2;
#pragma unroll
    for (int s = 0; s < 4; s++) {
        int oc0 = s * 16 + (l >> 2);
        int oc1 = oc0 + 8;
        float sc0 = scale[oc0], bi0 = bias[oc0];
        float sc1 = scale[oc1], bi1 = bias[oc1];
        float2 v0 = make_float2(fmaxf(acc[s][0] * sc0 + bi0, 0.f),
                                fmaxf(acc[s][1] * sc0 + bi0, 0.f));
        float2 v1 = make_float2(fmaxf(acc[s][2] * sc1 + bi1, 0.f),
                                fmaxf(acc[s][3] * sc1 + bi1, 0.f));
        *(float2*)&g_s[((b * 64 + oc0) * 64 + ho) * 64 + col] = v0;
        *(float2*)&g_s[((b * 64 + oc1) * 64 + ho) * 64 + col] = v1;
    }
}

// ---------------------------------------------------------------------------
// conv5 (5x5, pad 2) + BN3 + ReLU, accumulated into g_s — tf32 mma
// ---------------------------------------------------------------------------
__global__ __launch_bounds__(256) void conv5_mma_kernel(
    const float* __restrict__ x,
    const float* __restrict__ gg, const float* __restrict__ bbn,
    const float* __restrict__ mmn, const float* __restrict__ vvn)
{
    extern __shared__ unsigned cm[];
    unsigned* xs  = cm;                      // [16][12][22]
    unsigned* wfr = cm + 4224;               // [5 kx][2 c8][4 strip][128]
    float* scale  = (float*)(cm + 4224 + 5120);
    float* bias   = scale + 64;

    int tid = threadIdx.x;
    int l   = tid & 31, wp = tid >> 5;
    int b   = blockIdx.y;
    int by0 = (blockIdx.x >> 2) * 8;
    int bx0 = (blockIdx.x & 3) * 16;

    if (tid < 64) {
        float sc   = gg[tid] * rsqrtf(vvn[tid] + 1e-5f);
        scale[tid] = sc;
        bias[tid]  = bbn[tid] - mmn[tid] * sc;
    }

    float acc[4][2][4];
#pragma unroll
    for (int s = 0; s < 4; s++)
#pragma unroll
        for (int g = 0; g < 2; g++)
#pragma unroll
            for (int r = 0; r < 4; r++) acc[s][g][r] = 0.f;

    const unsigned* bbase = xs + (l & 3) * 264 + wp * 22 + (l >> 2);

    for (int cblk = 0; cblk < 4; cblk++) {
        __syncthreads();
        for (int i = tid; i < 3840; i += 256) {
            int c = i / 240, rr = i % 240, yy = rr / 20, xx = rr % 20;
            int gy = by0 - 2 + yy, gx = bx0 - 2 + xx;
            float v = 0.f;
            if (gy >= 0 && gy < 64 && gx >= 0 && gx < 64)
                v = x[((b * 64 + cblk * 16 + c) * 64 + gy) * 64 + gx];
            xs[(c * 12 + yy) * 22 + xx] = f2tf(v);
        }
        for (int ky = 0; ky < 5; ky++) {
            __syncthreads();
            for (int i4 = tid; i4 < 1280; i4 += 256) {
                int tl = i4 >> 8, rest = i4 & 255;
                ((uint4*)wfr)[i4] =
                    ((const uint4*)(g_wpk5 + (ky * 5 + tl) * 4096 + cblk * 1024))[rest];
            }
            __syncthreads();
#pragma unroll
            for (int kx = 0; kx < 5; kx++) {
#pragma unroll
                for (int c8 = 0; c8 < 2; c8++) {
                    unsigned A[4][4];
#pragma unroll
                    for (int s = 0; s < 4; s++)
                        *(uint4*)A[s] = *(const uint4*)(wfr + (kx * 2 + c8) * 512 + s * 128 + l * 4);
#pragma unroll
                    for (int g = 0; g < 2; g++) {
                        unsigned bf[2];
                        bf[0] = bbase[c8 * 2112 + ky * 22 + g * 8 + kx];
                        bf[1] = bbase[c8 * 2112 + 1056 + ky * 22 + g * 8 + kx];
#pragma unroll
                        for (int s = 0; s < 4; s++) mma8(acc[s][g], A[s], bf);
                    }
                }
            }
        }
    }

    int row_g = by0 + wp;
#pragma unroll
    for (int s = 0; s < 4; s++) {
#pragma unroll
        for (int g = 0; g < 2; g++) {
            int oc0 = s * 16 + (l >> 2);
            int oc1 = oc0 + 8;
            int col = bx0 + g * 8 + (l & 3) * 2;
            float sc0 = scale[oc0], bi0 = bias[oc0];
            float sc1 = scale[oc1], bi1 = bias[oc1];
            float* a0 = &g_s[((b * 64 + oc0) * 64 + row_g) * 64 + col];
            float* a1 = &g_s[((b * 64 + oc1) * 64 + row_g) * 64 + col];
            float2 o0 = *(float2*)a0;
            float2 o1 = *(float2*)a1;
            o0.x += fmaxf(acc[s][g][0] * sc0 + bi0, 0.f);
            o0.y += fmaxf(acc[s][g][1] * sc0 + bi0, 0.f);
            o1.x += fmaxf(acc[s][g][2] * sc1 + bi1, 0.f);
            o1.y += fmaxf(acc[s][g][3] * sc1 + bi1, 0.f);
            *(float2*)a0 = o0;
            *(float2*)a1 = o1;
        }
    }
}

// ---------------------------------------------------------------------------
// Final conv: 3x3, pad 1, on g_s, + BN2 + residual + ReLU -> dst — tf32 mma
// ---------------------------------------------------------------------------
__global__ __launch_bounds__(256) void conv3_mma_kernel(
    const float* __restrict__ gg, const float* __restrict__ bbn,
    const float* __restrict__ mmn, const float* __restrict__ vvn,
    const float* __restrict__ resid, float* __restrict__ dst)
{
    extern __shared__ unsigned c3[];
    unsigned* xs  = c3;                      // [16 c][10 y][20 x] = 3200
    unsigned* wfr = c3 + 3200;               // [3 kx][2 c8][4 strip][128] = 3072
    float* scale  = (float*)(c3 + 3200 + 3072);
    float* bias   = scale + 64;

    int tid = threadIdx.x;
    int l   = tid & 31, wp = tid >> 5;
    int b   = blockIdx.y;
    int by0 = (blockIdx.x >> 2) * 8;
    int bx0 = (blockIdx.x & 3) * 16;

    if (tid < 64) {
        float sc   = gg[tid] * rsqrtf(vvn[tid] + 1e-5f);
        scale[tid] = sc;
        bias[tid]  = bbn[tid] - mmn[tid] * sc;
    }

    float acc[4][2][4];
#pragma unroll
    for (int s = 0; s < 4; s++)
#pragma unroll
        for (int g = 0; g < 2; g++)
#pragma unroll
            for (int r = 0; r < 4; r++) acc[s][g][r] = 0.f;

    const unsigned* bbase = xs + (l & 3) * 200 + wp * 20 + (l >> 2);

    for (int cblk = 0; cblk < 4; cblk++) {
        __syncthreads();
        for (int i = tid; i < 2880; i += 256) {
            int c = i / 180, rr = i % 180, yy = rr / 18, xx = rr % 18;
            int gy = by0 - 1 + yy, gx = bx0 - 1 + xx;
            float v = 0.f;
            if (gy >= 0 && gy < 64 && gx >= 0 && gx < 64)
                v = g_s[((b * 64 + cblk * 16 + c) * 64 + gy) * 64 + gx];
            xs[(c * 10 + yy) * 20 + xx] = f2tf(v);
        }
        for (int ky = 0; ky < 3; ky++) {
            __syncthreads();
            for (int i4 = tid; i4 < 768; i4 += 256) {
                int tl = i4 >> 8, rest = i4 & 255;
                ((uint4*)wfr)[i4] =
                    ((const uint4*)(g_wpk3 + (ky * 3 + tl) * 4096 + cblk * 1024))[rest];
            }
            __syncthreads();
#pragma unroll
            for (int kx = 0; kx < 3; kx++) {
#pragma unroll
                for (int c8 = 0; c8 < 2; c8++) {
                    unsigned A[4][4];
#pragma unroll
                    for (int s = 0; s < 4; s++)
                        *(uint4*)A[s] = *(const uint4*)(wfr + (kx * 2 + c8) * 512 + s * 128 + l * 4);
#pragma unroll
                    for (int g = 0; g < 2; g++) {
                        unsigned bf[2];
                        bf[0] = bbase[c8 * 1600 + ky * 20 + g * 8 + kx];
                        bf[1] = bbase[c8 * 1600 + 800 + ky * 20 + g * 8 + kx];
#pragma unroll
                        for (int s = 0; s < 4; s++) mma8(acc[s][g], A[s], bf);
                    }
                }
            }
        }
    }

    int row_g = by0 + wp;
#pragma unroll
    for (int s = 0; s < 4; s++) {
#pragma unroll
        for (int g = 0; g < 2; g++) {
            int oc0 = s * 16 + (l >> 2);
            int oc1 = oc0 + 8;
            int col = bx0 + g * 8 + (l & 3) * 2;
            float sc0 = scale[oc0], bi0 = bias[oc0];
            float sc1 = scale[oc1], bi1 = bias[oc1];
            int i0 = ((b * 64 + oc0) * 64 + row_g) * 64 + col;
            int i1 = ((b * 64 + oc1) * 64 + row_g) * 64 + col;
            float2 r0 = *(const float2*)&resid[i0];
            float2 r1 = *(const float2*)&resid[i1];
            float2 o0 = make_float2(
                fmaxf(acc[s][g][0] * sc0 + bi0 + r0.x, 0.f),
                fmaxf(acc[s][g][1] * sc0 + bi0 + r0.y, 0.f));
            float2 o1 = make_float2(
                fmaxf(acc[s][g][2] * sc1 + bi1 + r1.x, 0.f),
                fmaxf(acc[s][g][3] * sc1 + bi1 + r1.y, 0.f));
            *(float2*)&dst[i0] = o0;
            *(float2*)&dst[i1] = o1;
        }
    }
}

// ---------------------------------------------------------------------------
extern "C" void kernel_launch(void* const* d_in, const int* in_sizes, int n_in,
                              void* d_out, int out_size)
{
    const float* x     = (const float*)d_in[0];
    const float* w_off = (const float*)d_in[1];
    const float* b_off = (const float*)d_in[2];
    const float* w1    = (const float*)d_in[3];
    const float* g1    = (const float*)d_in[4];
    const float* b1    = (const float*)d_in[5];
    const float* m1    = (const float*)d_in[6];
    const float* v1    = (const float*)d_in[7];
    const float* w3    = (const float*)d_in[8];
    const float* g3    = (const float*)d_in[9];
    const float* b3    = (const float*)d_in[10];
    const float* m3    = (const float*)d_in[11];
    const float* v3    = (const float*)d_in[12];
    const float* w2    = (const float*)d_in[13];
    const float* g2    = (const float*)d_in[14];
    const float* b2    = (const float*)d_in[15];
    const float* m2    = (const float*)d_in[16];
    const float* v2    = (const float*)d_in[17];
    float* out = (float*)d_out;

    const int smemD = 83712;                        // deform (2 CTA/SM)
    const int smem5 = (4224 + 5120 + 128) * 4;      // 37,888
    const int smem3 = (3200 + 3072 + 128) * 4;      // 25,600
    const int smemO = (3200 + 1536) * 4;            // 18,944
    static bool attr_set = false;
    if (!attr_set) {
        cudaFuncSetAttribute(deform_mma_kernel,
                             cudaFuncAttributeMaxDynamicSharedMemorySize, smemD);
        cudaFuncSetAttribute(conv5_mma_kernel,
                             cudaFuncAttributeMaxDynamicSharedMemorySize, smem5);
        cudaFuncSetAttribute(conv3_mma_kernel,
                             cudaFuncAttributeMaxDynamicSharedMemorySize, smem3);
        cudaFuncSetAttribute(offset_mma_kernel,
                             cudaFuncAttributeMaxDynamicSharedMemorySize, smemO);
        attr_set = true;
    }

    transpose_kernel<<<dim3(64, 16), 256>>>(x);
    repack_all_kernel<<<760, 256>>>(w3, w1, w2, w_off);
    offset_mma_kernel<<<dim3(32, 16), 256, smemO>>>(x, b_off);
    deform_mma_kernel<<<dim3(64, 16), 256, smemD>>>(g1, b1, m1, v1);
    conv5_mma_kernel<<<dim3(32, 16), 256, smem5>>>(x, g3, b3, m3, v3);
    conv3_mma_kernel<<<dim3(32, 16), 256, smem3>>>(g2, b2, m2, v2, x, out);
}

// round 9
// speedup vs baseline: 3.4412x; 1.0201x over previous
#include <cuda_runtime.h>
#include <cuda_fp16.h>

#define HW 4096
typedef unsigned long long ull;

__device__ float  g_off[16 * 18 * HW];     // offsets from offset conv
__device__ float  g_s[16 * 64 * HW];       // branch-sum feature map
__device__ __half g_xth[16 * 64 * HW];     // x transposed to NHWC fp16
__device__ unsigned g_wpk5[102400];        // w3 fragment-packed (tf32 bits)
__device__ unsigned g_wpk1[36864];         // w1 fragment-packed
__device__ unsigned g_wpk3[36864];         // w2 fragment-packed
__device__ unsigned g_wpko[18432];         // w_off fragment-packed (oc pad 32)

// ---- tf32 mma helpers ------------------------------------------------------
__device__ __forceinline__ unsigned f2tf(float f) {
    unsigned u;
    asm("cvt.rna.tf32.f32 %0, %1;" : "=r"(u) : "f"(f));
    return u;
}
__device__ __forceinline__ void mma8(float* d, const unsigned* a, const unsigned* b) {
    asm("mma.sync.aligned.m16n8k8.row.col.f32.tf32.tf32.f32 "
        "{%0,%1,%2,%3},{%4,%5,%6,%7},{%8,%9},{%0,%1,%2,%3};"
        : "+f"(d[0]), "+f"(d[1]), "+f"(d[2]), "+f"(d[3])
        : "r"(a[0]), "r"(a[1]), "r"(a[2]), "r"(a[3]), "r"(b[0]), "r"(b[1]));
}

// ---------------------------------------------------------------------------
// Transpose x NCHW -> NHWC fp16 (g_xth)
// ---------------------------------------------------------------------------
__global__ __launch_bounds__(256) void transpose_kernel(const float* __restrict__ x)
{
    __shared__ float t[64][65];
    int tid = threadIdx.x;
    int y = blockIdx.x, b = blockIdx.y;
    const float* xb = x + (b * 64) * HW + y * 64;
#pragma unroll
    for (int i = 0; i < 16; i++) {
        int c = i * 4 + (tid >> 6), xc = tid & 63;
        t[xc][c] = xb[c * HW + xc];
    }
    __syncthreads();
    __half* ob = g_xth + ((b * 64 + y) * 64) * 64;
#pragma unroll
    for (int i = 0; i < 16; i++) {
        int xc = i * 4 + (tid >> 6), c = tid & 63;
        ob[xc * 64 + c] = __float2half(t[xc][c]);
    }
}

// ---------------------------------------------------------------------------
// All weight repacks in ONE kernel (tf32-rounded, mma A-fragment order)
// ---------------------------------------------------------------------------
__global__ void repack_all_kernel(const float* __restrict__ w3,
                                  const float* __restrict__ w1,
                                  const float* __restrict__ w2,
                                  const float* __restrict__ w_off)
{
    int i = blockIdx.x * 256 + threadIdx.x;
    if (i < 102400) {
        int r = i & 3, lane = (i >> 2) & 31, strip = (i >> 7) & 3;
        int c8 = (i >> 9) & 1, cblk = (i >> 10) & 3, tap = i >> 12;
        int oc = strip * 16 + (lane >> 2) + (r & 1) * 8;
        int c  = cblk * 16 + c8 * 8 + (lane & 3) + (r >> 1) * 4;
        g_wpk5[i] = f2tf(w3[(oc * 64 + c) * 25 + tap]);
    } else if (i < 139264) {
        int j = i - 102400;
        int r = j & 3, lane = (j >> 2) & 31, strip = (j >> 7) & 3, kstep = j >> 9;
        int oc = strip * 16 + (lane >> 2) + (r & 1) * 8;
        int K  = kstep * 8 + (lane & 3) + (r >> 1) * 4;
        int tap = K >> 6, c = K & 63;
        g_wpk1[j] = f2tf(w1[(oc * 64 + c) * 9 + tap]);
    } else if (i < 176128) {
        int j = i - 139264;
        int r = j & 3, lane = (j >> 2) & 31, strip = (j >> 7) & 3;
        int c8 = (j >> 9) & 1, cblk = (j >> 10) & 3, tap = j >> 12;
        int oc = strip * 16 + (lane >> 2) + (r & 1) * 8;
        int c  = cblk * 16 + c8 * 8 + (lane & 3) + (r >> 1) * 4;
        g_wpk3[j] = f2tf(w2[(oc * 64 + c) * 9 + tap]);
    } else if (i < 194560) {
        int j = i - 176128;
        int r = j & 3, lane = (j >> 2) & 31, strip = (j >> 7) & 1;
        int c8 = (j >> 8) & 1, cblk = (j >> 9) & 3, tap = j >> 11;
        int oc = strip * 16 + (lane >> 2) + (r & 1) * 8;
        int c  = cblk * 16 + c8 * 8 + (lane & 3) + (r >> 1) * 4;
        g_wpko[j] = (oc < 18) ? f2tf(w_off[(oc * 64 + c) * 9 + tap]) : 0u;
    }
}

// ---------------------------------------------------------------------------
// Offset conv as tf32 MMA implicit GEMM (direct-LDG A fragments)
// ---------------------------------------------------------------------------
__global__ __launch_bounds__(256) void offset_mma_kernel(
    const float* __restrict__ x, const float* __restrict__ b_off)
{
    extern __shared__ unsigned om[];
    unsigned* xs = om;            // [16 c][10 y][20 x] = 3200

    int tid = threadIdx.x;
    int l   = tid & 31, wp = tid >> 5;
    int b   = blockIdx.y;
    int by0 = (blockIdx.x >> 2) * 8;
    int bx0 = (blockIdx.x & 3) * 16;

    float acc[2][2][4];
#pragma unroll
    for (int s = 0; s < 2; s++)
#pragma unroll
        for (int g = 0; g < 2; g++)
#pragma unroll
            for (int r = 0; r < 4; r++) acc[s][g][r] = 0.f;

    const unsigned* bbase = xs + (l & 3) * 200 + wp * 20 + (l >> 2);

    for (int cblk = 0; cblk < 4; cblk++) {
        __syncthreads();
        for (int i = tid; i < 2880; i += 256) {
            int c = i / 180, rr = i % 180, yy = rr / 18, xx = rr % 18;
            int gy = by0 - 1 + yy, gx = bx0 - 1 + xx;
            float v = 0.f;
            if (gy >= 0 && gy < 64 && gx >= 0 && gx < 64)
                v = x[((b * 64 + cblk * 16 + c) * 64 + gy) * 64 + gx];
            xs[(c * 10 + yy) * 20 + xx] = f2tf(v);
        }
        __syncthreads();
#pragma unroll
        for (int ky = 0; ky < 3; ky++)
#pragma unroll
        for (int kx = 0; kx < 3; kx++) {
#pragma unroll
            for (int c8 = 0; c8 < 2; c8++) {
                unsigned A[2][4];
#pragma unroll
                for (int s = 0; s < 2; s++)
                    *(uint4*)A[s] = *(const uint4*)(g_wpko +
                        (ky * 3 + kx) * 2048 + cblk * 512 + c8 * 256 + s * 128 + l * 4);
#pragma unroll
                for (int g = 0; g < 2; g++) {
                    unsigned bf[2];
                    bf[0] = bbase[c8 * 1600 + ky * 20 + g * 8 + kx];
                    bf[1] = bbase[c8 * 1600 + 800 + ky * 20 + g * 8 + kx];
#pragma unroll
                    for (int s = 0; s < 2; s++) mma8(acc[s][g], A[s], bf);
                }
            }
        }
    }

    int row_g = by0 + wp;
#pragma unroll
    for (int s = 0; s < 2; s++) {
#pragma unroll
        for (int g = 0; g < 2; g++) {
            int oc0 = s * 16 + (l >> 2);
            int oc1 = oc0 + 8;
            int col = bx0 + g * 8 + (l & 3) * 2;
            if (oc0 < 18) {
                float bi = b_off[oc0];
                float* o = &g_off[((b * 18 + oc0) * 64 + row_g) * 64 + col];
                o[0] = acc[s][g][0] + bi;
                o[1] = acc[s][g][1] + bi;
            }
            if (oc1 < 18) {
                float bi = b_off[oc1];
                float* o = &g_off[((b * 18 + oc1) * 64 + row_g) * 64 + col];
                o[0] = acc[s][g][2] + bi;
                o[1] = acc[s][g][3] + bi;
            }
        }
    }
}

// ---------------------------------------------------------------------------
// Deformable conv (3x3, pad 1) + BN1 + ReLU -> g_s, tf32 mma GEMM
// v5: val[px][K] with group-padded rows (conflict-free STS.128 writes +
// conflict-free B-frag reads), 1-tap chunks, direct-LDG A fragments.
// ---------------------------------------------------------------------------
__global__ __launch_bounds__(256) void deform_mma_kernel(
    const float* __restrict__ g1, const float* __restrict__ b1,
    const float* __restrict__ m1, const float* __restrict__ v1)
{
    extern __shared__ unsigned dm[];
    unsigned* val = dm;                          // [64 px][100] (1 tap: 4 grp x 24 + pad)
    float* cw00   = (float*)(dm + 6400);         // [576]
    float* cw01   = cw00 + 576;
    float* cw10   = cw01 + 576;
    float* cw11   = cw10 + 576;
    int*   cpos   = (int*)(cw11 + 576);          // [576]
    float* scale  = (float*)(cpos + 576);        // [64]
    float* bias   = scale + 64;                  // [64]

    int tid = threadIdx.x;
    int l   = tid & 31, wp = tid >> 5;
    int ho  = blockIdx.x, b = blockIdx.y;

    if (tid < 64) {
        float sc   = g1[tid] * rsqrtf(v1[tid] + 1e-5f);
        scale[tid] = sc;
        bias[tid]  = b1[tid] - m1[tid] * sc;
    }
    for (int t = tid; t < 576; t += 256) {
        int k = t >> 6, px = t & 63;
        int ky = k / 3, kx = k % 3;
        int wo = px;
        float dy = g_off[((b * 18 + 2 * k) * 64 + ho) * 64 + wo];
        float dx = g_off[((b * 18 + 2 * k + 1) * 64 + ho) * 64 + wo];
        float ys  = (float)(ho - 1 + ky) + dy;
        float xsm = (float)(wo - 1 + kx) + dx;
        float y0f = floorf(ys), x0f = floorf(xsm);
        float y1f = y0f + 1.f, x1f = x0f + 1.f;
        float wy1 = ys - y0f, wx1 = xsm - x0f;
        float wy0 = 1.f - wy1, wx0 = 1.f - wx1;
        bool vy0 = (y0f >= 0.f) && (y0f <= 63.f);
        bool vy1 = (y1f >= 0.f) && (y1f <= 63.f);
        bool vx0 = (x0f >= 0.f) && (x0f <= 63.f);
        bool vx1 = (x1f >= 0.f) && (x1f <= 63.f);
        cw00[t] = (vy0 && vx0) ? wy0 * wx0 : 0.f;
        cw01[t] = (vy0 && vx1) ? wy0 * wx1 : 0.f;
        cw10[t] = (vy1 && vx0) ? wy1 * wx0 : 0.f;
        cw11[t] = (vy1 && vx1) ? wy1 * wx1 : 0.f;
        int y0c = (int)fminf(fmaxf(y0f, 0.f), 63.f);
        int x0c = (int)fminf(fmaxf(x0f, 0.f), 63.f);
        int y1c = (int)fminf(fmaxf(y1f, 0.f), 63.f);
        int x1c = (int)fminf(fmaxf(x1f, 0.f), 63.f);
        cpos[t] = y0c | (x0c << 6) | (y1c << 12) | (x1c << 18);
    }

    float acc[4][4];
#pragma unroll
    for (int s = 0; s < 4; s++)
#pragma unroll
        for (int r = 0; r < 4; r++) acc[s][r] = 0.f;

    int cg = tid & 3;
    int px = tid >> 2;

    __syncthreads();   // coeffs ready

    for (int kc = 0; kc < 9; kc++) {
        if (kc) __syncthreads();   // prev GEMM done reading val

        // gather tap kc: one task per thread (cg, px)
        {
            int pair = kc * 64 + px;
            int p  = cpos[pair];
            float w00 = cw00[pair], w01 = cw01[pair];
            float w10 = cw10[pair], w11 = cw11[pair];
            int y0 = p & 63, x0 = (p >> 6) & 63;
            int y1 = (p >> 12) & 63, x1 = (p >> 18) & 63;
            const uint4* p00 = (const uint4*)(g_xth + (((b * 64 + y0) * 64 + x0) * 64) + cg * 16);
            const uint4* p01 = (const uint4*)(g_xth + (((b * 64 + y0) * 64 + x1) * 64) + cg * 16);
            const uint4* p10 = (const uint4*)(g_xth + (((b * 64 + y1) * 64 + x0) * 64) + cg * 16);
            const uint4* p11 = (const uint4*)(g_xth + (((b * 64 + y1) * 64 + x1) * 64) + cg * 16);
            unsigned tmp[16];
#pragma unroll
            for (int h = 0; h < 2; h++) {
                uint4 q00 = p00[h], q01 = p01[h], q10 = p10[h], q11 = p11[h];
                const __half2* h00 = (const __half2*)&q00;
                const __half2* h01 = (const __half2*)&q01;
                const __half2* h10 = (const __half2*)&q10;
                const __half2* h11 = (const __half2*)&q11;
#pragma unroll
                for (int j = 0; j < 4; j++) {
                    float2 c00 = __half22float2(h00[j]);
                    float2 c01 = __half22float2(h01[j]);
                    float2 c10 = __half22float2(h10[j]);
                    float2 c11 = __half22float2(h11[j]);
                    float r0 = w00 * c00.x + w01 * c01.x + w10 * c10.x + w11 * c11.x;
                    float r1 = w00 * c00.y + w01 * c01.y + w10 * c10.y + w11 * c11.y;
                    tmp[h * 8 + j * 2]     = f2tf(r0);
                    tmp[h * 8 + j * 2 + 1] = f2tf(r1);
                }
            }
            uint4* vout = (uint4*)(val + px * 100 + cg * 24);
#pragma unroll
            for (int q = 0; q < 4; q++)
                vout[q] = *(const uint4*)&tmp[q * 4];
        }
        __syncthreads();   // val ready

        // GEMM for tap kc: 8 ksteps, A-frags direct from global
#pragma unroll
        for (int ks = 0; ks < 8; ks++) {
            unsigned A[4][4];
#pragma unroll
            for (int s = 0; s < 4; s++)
                *(uint4*)A[s] = *(const uint4*)(g_wpk1 + kc * 4096 + (ks * 4 + s) * 128 + l * 4);
            const unsigned* bp = val + (wp * 8 + (l >> 2)) * 100
                                 + (ks >> 1) * 24 + (ks & 1) * 8 + (l & 3);
            unsigned bf[2];
            bf[0] = bp[0];
            bf[1] = bp[4];
#pragma unroll
            for (int s = 0; s < 4; s++) mma8(acc[s], A[s], bf);
        }
    }

    int col = wp * 8 + (l & 3) * 2;
#pragma unroll
    for (int s = 0; s < 4; s++) {
        int oc0 = s * 16 + (l >> 2);
        int oc1 = oc0 + 8;
        float sc0 = scale[oc0], bi0 = bias[oc0];
        float sc1 = scale[oc1], bi1 = bias[oc1];
        float2 v0 = make_float2(fmaxf(acc[s][0] * sc0 + bi0, 0.f),
                                fmaxf(acc[s][1] * sc0 + bi0, 0.f));
        float2 v1 = make_float2(fmaxf(acc[s][2] * sc1 + bi1, 0.f),
                                fmaxf(acc[s][3] * sc1 + bi1, 0.f));
        *(float2*)&g_s[((b * 64 + oc0) * 64 + ho) * 64 + col] = v0;
        *(float2*)&g_s[((b * 64 + oc1) * 64 + ho) * 64 + col] = v1;
    }
}

// ---------------------------------------------------------------------------
// conv5 (5x5, pad 2) + BN3 + ReLU, accumulated into g_s — tf32 mma
// (direct-LDG A fragments, no weight staging)
// ---------------------------------------------------------------------------
__global__ __launch_bounds__(256) void conv5_mma_kernel(
    const float* __restrict__ x,
    const float* __restrict__ gg, const float* __restrict__ bbn,
    const float* __restrict__ mmn, const float* __restrict__ vvn)
{
    extern __shared__ unsigned cm[];
    unsigned* xs  = cm;                      // [16][12][22] = 4224
    float* scale  = (float*)(cm + 4224);
    float* bias   = scale + 64;

    int tid = threadIdx.x;
    int l   = tid & 31, wp = tid >> 5;
    int b   = blockIdx.y;
    int by0 = (blockIdx.x >> 2) * 8;
    int bx0 = (blockIdx.x & 3) * 16;

    if (tid < 64) {
        float sc   = gg[tid] * rsqrtf(vvn[tid] + 1e-5f);
        scale[tid] = sc;
        bias[tid]  = bbn[tid] - mmn[tid] * sc;
    }

    float acc[4][2][4];
#pragma unroll
    for (int s = 0; s < 4; s++)
#pragma unroll
        for (int g = 0; g < 2; g++)
#pragma unroll
            for (int r = 0; r < 4; r++) acc[s][g][r] = 0.f;

    const unsigned* bbase = xs + (l & 3) * 264 + wp * 22 + (l >> 2);

    for (int cblk = 0; cblk < 4; cblk++) {
        __syncthreads();
        for (int i = tid; i < 3840; i += 256) {
            int c = i / 240, rr = i % 240, yy = rr / 20, xx = rr % 20;
            int gy = by0 - 2 + yy, gx = bx0 - 2 + xx;
            float v = 0.f;
            if (gy >= 0 && gy < 64 && gx >= 0 && gx < 64)
                v = x[((b * 64 + cblk * 16 + c) * 64 + gy) * 64 + gx];
            xs[(c * 12 + yy) * 22 + xx] = f2tf(v);
        }
        __syncthreads();
        for (int ky = 0; ky < 5; ky++) {
#pragma unroll
            for (int kx = 0; kx < 5; kx++) {
#pragma unroll
                for (int c8 = 0; c8 < 2; c8++) {
                    unsigned A[4][4];
#pragma unroll
                    for (int s = 0; s < 4; s++)
                        *(uint4*)A[s] = *(const uint4*)(g_wpk5 +
                            (ky * 5 + kx) * 4096 + cblk * 1024 + c8 * 512 + s * 128 + l * 4);
#pragma unroll
                    for (int g = 0; g < 2; g++) {
                        unsigned bf[2];
                        bf[0] = bbase[c8 * 2112 + ky * 22 + g * 8 + kx];
                        bf[1] = bbase[c8 * 2112 + 1056 + ky * 22 + g * 8 + kx];
#pragma unroll
                        for (int s = 0; s < 4; s++) mma8(acc[s][g], A[s], bf);
                    }
                }
            }
        }
    }

    int row_g = by0 + wp;
#pragma unroll
    for (int s = 0; s < 4; s++) {
#pragma unroll
        for (int g = 0; g < 2; g++) {
            int oc0 = s * 16 + (l >> 2);
            int oc1 = oc0 + 8;
            int col = bx0 + g * 8 + (l & 3) * 2;
            float sc0 = scale[oc0], bi0 = bias[oc0];
            float sc1 = scale[oc1], bi1 = bias[oc1];
            float* a0 = &g_s[((b * 64 + oc0) * 64 + row_g) * 64 + col];
            float* a1 = &g_s[((b * 64 + oc1) * 64 + row_g) * 64 + col];
            float2 o0 = *(float2*)a0;
            float2 o1 = *(float2*)a1;
            o0.x += fmaxf(acc[s][g][0] * sc0 + bi0, 0.f);
            o0.y += fmaxf(acc[s][g][1] * sc0 + bi0, 0.f);
            o1.x += fmaxf(acc[s][g][2] * sc1 + bi1, 0.f);
            o1.y += fmaxf(acc[s][g][3] * sc1 + bi1, 0.f);
            *(float2*)a0 = o0;
            *(float2*)a1 = o1;
        }
    }
}

// ---------------------------------------------------------------------------
// Final conv: 3x3, pad 1, on g_s, + BN2 + residual + ReLU -> dst — tf32 mma
// (direct-LDG A fragments)
// ---------------------------------------------------------------------------
__global__ __launch_bounds__(256) void conv3_mma_kernel(
    const float* __restrict__ gg, const float* __restrict__ bbn,
    const float* __restrict__ mmn, const float* __restrict__ vvn,
    const float* __restrict__ resid, float* __restrict__ dst)
{
    extern __shared__ unsigned c3[];
    unsigned* xs  = c3;                      // [16 c][10 y][20 x] = 3200
    float* scale  = (float*)(c3 + 3200);
    float* bias   = scale + 64;

    int tid = threadIdx.x;
    int l   = tid & 31, wp = tid >> 5;
    int b   = blockIdx.y;
    int by0 = (blockIdx.x >> 2) * 8;
    int bx0 = (blockIdx.x & 3) * 16;

    if (tid < 64) {
        float sc   = gg[tid] * rsqrtf(vvn[tid] + 1e-5f);
        scale[tid] = sc;
        bias[tid]  = bbn[tid] - mmn[tid] * sc;
    }

    float acc[4][2][4];
#pragma unroll
    for (int s = 0; s < 4; s++)
#pragma unroll
        for (int g = 0; g < 2; g++)
#pragma unroll
            for (int r = 0; r < 4; r++) acc[s][g][r] = 0.f;

    const unsigned* bbase = xs + (l & 3) * 200 + wp * 20 + (l >> 2);

    for (int cblk = 0; cblk < 4; cblk++) {
        __syncthreads();
        for (int i = tid; i < 2880; i += 256) {
            int c = i / 180, rr = i % 180, yy = rr / 18, xx = rr % 18;
            int gy = by0 - 1 + yy, gx = bx0 - 1 + xx;
            float v = 0.f;
            if (gy >= 0 && gy < 64 && gx >= 0 && gx < 64)
                v = g_s[((b * 64 + cblk * 16 + c) * 64 + gy) * 64 + gx];
            xs[(c * 10 + yy) * 20 + xx] = f2tf(v);
        }
        __syncthreads();
#pragma unroll
        for (int ky = 0; ky < 3; ky++)
#pragma unroll
        for (int kx = 0; kx < 3; kx++) {
#pragma unroll
            for (int c8 = 0; c8 < 2; c8++) {
                unsigned A[4][4];
#pragma unroll
                for (int s = 0; s < 4; s++)
                    *(uint4*)A[s] = *(const uint4*)(g_wpk3 +
                        (ky * 3 + kx) * 4096 + cblk * 1024 + c8 * 512 + s * 128 + l * 4);
#pragma unroll
                for (int g = 0; g < 2; g++) {
                    unsigned bf[2];
                    bf[0] = bbase[c8 * 1600 + ky * 20 + g * 8 + kx];
                    bf[1] = bbase[c8 * 1600 + 800 + ky * 20 + g * 8 + kx];
#pragma unroll
                    for (int s = 0; s < 4; s++) mma8(acc[s][g], A[s], bf);
                }
            }
        }
    }

    int row_g = by0 + wp;
#pragma unroll
    for (int s = 0; s < 4; s++) {
#pragma unroll
        for (int g = 0; g < 2; g++) {
            int oc0 = s * 16 + (l >> 2);
            int oc1 = oc0 + 8;
            int col = bx0 + g * 8 + (l & 3) * 2;
            float sc0 = scale[oc0], bi0 = bias[oc0];
            float sc1 = scale[oc1], bi1 = bias[oc1];
            int i0 = ((b * 64 + oc0) * 64 + row_g) * 64 + col;
            int i1 = ((b * 64 + oc1) * 64 + row_g) * 64 + col;
            float2 r0 = *(const float2*)&resid[i0];
            float2 r1 = *(const float2*)&resid[i1];
            float2 o0 = make_float2(
                fmaxf(acc[s][g][0] * sc0 + bi0 + r0.x, 0.f),
                fmaxf(acc[s][g][1] * sc0 + bi0 + r0.y, 0.f));
            float2 o1 = make_float2(
                fmaxf(acc[s][g][2] * sc1 + bi1 + r1.x, 0.f),
                fmaxf(acc[s][g][3] * sc1 + bi1 + r1.y, 0.f));
            *(float2*)&dst[i0] = o0;
            *(float2*)&dst[i1] = o1;
        }
    }
}

// ---------------------------------------------------------------------------
extern "C" void kernel_launch(void* const* d_in, const int* in_sizes, int n_in,
                              void* d_out, int out_size)
{
    const float* x     = (const float*)d_in[0];
    const float* w_off = (const float*)d_in[1];
    const float* b_off = (const float*)d_in[2];
    const float* w1    = (const float*)d_in[3];
    const float* g1    = (const float*)d_in[4];
    const float* b1    = (const float*)d_in[5];
    const float* m1    = (const float*)d_in[6];
    const float* v1    = (const float*)d_in[7];
    const float* w3    = (const float*)d_in[8];
    const float* g3    = (const float*)d_in[9];
    const float* b3    = (const float*)d_in[10];
    const float* m3    = (const float*)d_in[11];
    const float* v3    = (const float*)d_in[12];
    const float* w2    = (const float*)d_in[13];
    const float* g2    = (const float*)d_in[14];
    const float* b2    = (const float*)d_in[15];
    const float* m2    = (const float*)d_in[16];
    const float* v2    = (const float*)d_in[17];
    float* out = (float*)d_out;

    const int smemD = (6400 + 4 * 576 + 576 + 128) * 4;   // 37,632
    const int smem5 = (4224 + 128) * 4;                   // 17,408
    const int smem3 = (3200 + 128) * 4;                   // 13,312
    const int smemO = 3200 * 4;                           // 12,800
    static bool attr_set = false;
    if (!attr_set) {
        cudaFuncSetAttribute(deform_mma_kernel,
                             cudaFuncAttributeMaxDynamicSharedMemorySize, smemD);
        cudaFuncSetAttribute(conv5_mma_kernel,
                             cudaFuncAttributeMaxDynamicSharedMemorySize, smem5);
        cudaFuncSetAttribute(conv3_mma_kernel,
                             cudaFuncAttributeMaxDynamicSharedMemorySize, smem3);
        cudaFuncSetAttribute(offset_mma_kernel,
                             cudaFuncAttributeMaxDynamicSharedMemorySize, smemO);
        attr_set = true;
    }

    transpose_kernel<<<dim3(64, 16), 256>>>(x);
    repack_all_kernel<<<760, 256>>>(w3, w1, w2, w_off);
    offset_mma_kernel<<<dim3(32, 16), 256, smemO>>>(x, b_off);
    deform_mma_kernel<<<dim3(64, 16), 256, smemD>>>(g1, b1, m1, v1);
    conv5_mma_kernel<<<dim3(32, 16), 256, smem5>>>(x, g3, b3, m3, v3);
    conv3_mma_kernel<<<dim3(32, 16), 256, smem3>>>(g2, b2, m2, v2, x, out);
}